// round 6
// baseline (speedup 1.0000x reference)
#include <cuda_runtime.h>
#include <cuda_bf16.h>
#include <math.h>

// ---------------- problem constants ----------------
#define BB_   8
#define NTOK  196
#define DD    768
#define NH    12
#define HD    64
#define MHOP  3072
#define BN    (BB_*NTOK)          // 1568
#define NELEM (BN*DD)             // 1204224
#define BETA  0.125f              // 1/sqrt(64)
#define INVB  8.0f

// ---------------- scratch (no cudaMalloc allowed) ----------------
__device__ __align__(256) float d_g [4L*BN*DD];
__device__ __align__(256) float d_K [4L*BN*DD];
__device__ __align__(256) float d_Q [4L*BN*DD];
__device__ __align__(256) float d_h [(long)BN*MHOP];
__device__ __align__(256) float d_dK[BN*DD];
__device__ __align__(256) float d_dQ[BN*DD];
__device__ __align__(256) float d_dg[BN*DD];
__device__ __align__(256) float d_gr[BN*DD];
__device__ float  d_mean[BN];
__device__ float  d_rstd[BN];
__device__ double d_eref;
__device__ double d_ecand[4];
__device__ float  d_chosen;
__constant__ float c_lrs[4] = {1.0f, 0.5f, 0.25f, 0.125f};

// ---------------- tiny kernels ----------------
__global__ void zero_kernel() {
    if (threadIdx.x == 0) d_eref = 0.0;
    if (threadIdx.x < 4)  d_ecand[threadIdx.x] = 0.0;
}

__global__ void select_kernel() {
    if (threadIdx.x == 0) {
        double eref = d_eref;
        float chosen = 0.0625f;
        if (d_ecand[3] < eref) chosen = 0.125f;
        if (d_ecand[2] < eref) chosen = 0.25f;
        if (d_ecand[1] < eref) chosen = 0.5f;
        if (d_ecand[0] < eref) chosen = 1.0f;
        d_chosen = chosen;
    }
}

__global__ void update_kernel(const float* __restrict__ x,
                              const float* __restrict__ grad,
                              float* __restrict__ out) {
    int i = blockIdx.x * 256 + threadIdx.x;
    if (i < NELEM) out[i] = x[i] - d_chosen * grad[i];
}

// ---------------- LayerNorm forward (optionally fused candidate build) ----------------
__global__ void ln_fwd_kernel(const float* __restrict__ x,
                              const float* __restrict__ grad,   // null for main
                              float* __restrict__ gout,
                              const float* __restrict__ gamma,
                              const float* __restrict__ delta,
                              float* meanOut, float* rstdOut, int useLr) {
    int t = blockIdx.x, z = blockIdx.z, tid = threadIdx.x;
    const float lr = useLr ? c_lrs[z] : 0.f;
    const float* xr = x + (long)t * DD;
    float v[3]; float s = 0.f;
#pragma unroll
    for (int i = 0; i < 3; i++) {
        int c = tid + i * 256;
        float xv = xr[c];
        if (useLr) xv -= lr * grad[(long)t * DD + c];
        v[i] = xv; s += xv;
    }
    __shared__ float red[256];
    red[tid] = s; __syncthreads();
    for (int o = 128; o; o >>= 1) { if (tid < o) red[tid] += red[tid + o]; __syncthreads(); }
    float mu = red[0] * (1.f / DD);
    __syncthreads();
    float s2 = 0.f;
#pragma unroll
    for (int i = 0; i < 3; i++) { float dv = v[i] - mu; s2 += dv * dv; }
    red[tid] = s2; __syncthreads();
    for (int o = 128; o; o >>= 1) { if (tid < o) red[tid] += red[tid + o]; __syncthreads(); }
    float rs = rsqrtf(red[0] * (1.f / DD) + 1e-5f);
    float* orow = gout + (long)z * NELEM + (long)t * DD;
#pragma unroll
    for (int i = 0; i < 3; i++) {
        int c = tid + i * 256;
        orow[c] = gamma[c] * (v[i] - mu) * rs + delta[c];
    }
    if (!useLr && tid == 0) { meanOut[t] = mu; rstdOut[t] = rs; }
}

// ---------------- LayerNorm backward ----------------
__global__ void ln_bwd_kernel(const float* __restrict__ x,
                              const float* __restrict__ mean,
                              const float* __restrict__ rstd,
                              const float* __restrict__ gamma,
                              const float* __restrict__ dgv,
                              float* __restrict__ dx) {
    int t = blockIdx.x, tid = threadIdx.x;
    float mu = mean[t], rs = rstd[t];
    const float* xr = x + (long)t * DD;
    const float* dr = dgv + (long)t * DD;
    float xh[3], dxh[3]; float s1 = 0.f, s2 = 0.f;
#pragma unroll
    for (int i = 0; i < 3; i++) {
        int c = tid + i * 256;
        xh[i]  = (xr[c] - mu) * rs;
        dxh[i] = dr[c] * gamma[c];
        s1 += dxh[i]; s2 += dxh[i] * xh[i];
    }
    __shared__ float r1[256], r2[256];
    r1[tid] = s1; r2[tid] = s2; __syncthreads();
    for (int o = 128; o; o >>= 1) {
        if (tid < o) { r1[tid] += r1[tid + o]; r2[tid] += r2[tid + o]; }
        __syncthreads();
    }
    float m1 = r1[0] * (1.f / DD), m2 = r2[0] * (1.f / DD);
#pragma unroll
    for (int i = 0; i < 3; i++) {
        int c = tid + i * 256;
        dx[(long)t * DD + c] = rs * (dxh[i] - m1 - xh[i] * m2);
    }
}

// ---------------- bf16 3-term tensor-core GEMM ----------------
// Tile 128(M) x 64(N) x 16(K-step), 256 thr = 8 warps (4m x 2n), warp 32x32.
// Split: a = ah + al (bf16 each); acc += ah*bh + ah*bl + al*bh  (~fp16+ precision).
// TRANSB=1: B is [N,K] row-major (A*B^T). TRANSB=0: B is [K,N].
// epi: 0 = store alpha*acc (+=C if accumC)
//      1 = store relu(acc) to C AND accumulate -0.5*relu^2 into e_base
//      2 = energy only (no store)
__device__ __forceinline__ void split2(float x, float y, unsigned& hi, unsigned& lo) {
    __nv_bfloat16 hx = __float2bfloat16_rn(x), hy = __float2bfloat16_rn(y);
    __nv_bfloat162 h; h.x = hx; h.y = hy;
    hi = *(unsigned*)&h;
    __nv_bfloat162 l;
    l.x = __float2bfloat16_rn(x - __bfloat162float(hx));
    l.y = __float2bfloat16_rn(y - __bfloat162float(hy));
    lo = *(unsigned*)&l;
}

__device__ __forceinline__ void mma16(float* c, const unsigned* a, const unsigned* b) {
    asm volatile("mma.sync.aligned.m16n8k16.row.col.f32.bf16.bf16.f32 "
                 "{%0,%1,%2,%3}, {%4,%5,%6,%7}, {%8,%9}, {%0,%1,%2,%3};"
                 : "+f"(c[0]), "+f"(c[1]), "+f"(c[2]), "+f"(c[3])
                 : "r"(a[0]), "r"(a[1]), "r"(a[2]), "r"(a[3]),
                   "r"(b[0]), "r"(b[1]));
}

template <int TRANSB>
__global__ void __launch_bounds__(256, 2)
mma_gemm(const float* __restrict__ A, const float* __restrict__ B,
         float* __restrict__ C, int Mrows, int Ncols, int Kdim,
         float alpha, int accumC, int epi,
         double* e_base, int e_per_z, long strideAz, long strideCz) {
    // smem: u32-packed bf16 pairs; row = 8 u32 (16 bf16), XOR swizzle (col+row)&7
    __shared__ unsigned sA[2][2][128 * 8];   // [buf][split][row*8+swcol]
    __shared__ unsigned sB[2][2][64 * 8];

    const int tid = threadIdx.x;
    const int m0 = blockIdx.y * 128, n0 = blockIdx.x * 64;
    A += (long)blockIdx.z * strideAz;
    if (C) C += (long)blockIdx.z * strideCz;

    const int wid = tid >> 5, lane = tid & 31;
    const int wm = (wid >> 1) * 32, wn = (wid & 1) * 32;
    const int gr = lane >> 2, tg = lane & 3;

    float acc[2][4][4];
#pragma unroll
    for (int i = 0; i < 2; i++)
#pragma unroll
        for (int j = 0; j < 4; j++)
#pragma unroll
            for (int t = 0; t < 4; t++) acc[i][j][t] = 0.f;

    float ra[2][4], rbv[4];

    auto loadG = [&](int k0) {
#pragma unroll
        for (int it = 0; it < 2; it++) {               // A: 128 rows x 4 f4 = 512
            int idx = tid + it * 256;
            int r = idx >> 2, c4 = (idx & 3) * 4;
            float4 v = make_float4(0.f, 0.f, 0.f, 0.f);
            if (m0 + r < Mrows)
                v = *(const float4*)(A + (long)(m0 + r) * Kdim + k0 + c4);
            ra[it][0] = v.x; ra[it][1] = v.y; ra[it][2] = v.z; ra[it][3] = v.w;
        }
        float4 w;
        if (TRANSB) {                                   // 64 rows x 4 f4 = 256
            int r = tid >> 2, c4 = (tid & 3) * 4;
            w = *(const float4*)(B + (long)(n0 + r) * Kdim + k0 + c4);
        } else {                                        // 16 k x 16 n-groups
            int k = tid >> 4, nn4 = (tid & 15) * 4;
            w = *(const float4*)(B + (long)(k0 + k) * Ncols + n0 + nn4);
        }
        rbv[0] = w.x; rbv[1] = w.y; rbv[2] = w.z; rbv[3] = w.w;
    };

    auto storeS = [&](int buf) {
#pragma unroll
        for (int it = 0; it < 2; it++) {
            int idx = tid + it * 256;
            int r = idx >> 2, kq = (idx & 3) * 2;
            unsigned h0, l0, h1, l1;
            split2(ra[it][0], ra[it][1], h0, l0);
            split2(ra[it][2], ra[it][3], h1, l1);
            int b0 = r * 8 + ((kq + r) & 7);
            int b1 = r * 8 + ((kq + 1 + r) & 7);
            sA[buf][0][b0] = h0; sA[buf][0][b1] = h1;
            sA[buf][1][b0] = l0; sA[buf][1][b1] = l1;
        }
        if (TRANSB) {
            int r = tid >> 2, kq = (tid & 3) * 2;
            unsigned h0, l0, h1, l1;
            split2(rbv[0], rbv[1], h0, l0);
            split2(rbv[2], rbv[3], h1, l1);
            int b0 = r * 8 + ((kq + r) & 7);
            int b1 = r * 8 + ((kq + 1 + r) & 7);
            sB[buf][0][b0] = h0; sB[buf][0][b1] = h1;
            sB[buf][1][b0] = l0; sB[buf][1][b1] = l1;
        } else {
            int k = tid >> 4, n4 = (tid & 15) * 4;
            unsigned short* H = (unsigned short*)sB[buf][0];
            unsigned short* L = (unsigned short*)sB[buf][1];
#pragma unroll
            for (int j = 0; j < 4; j++) {
                int n = n4 + j;
                float v = rbv[j];
                __nv_bfloat16 h = __float2bfloat16_rn(v);
                __nv_bfloat16 l = __float2bfloat16_rn(v - __bfloat162float(h));
                int i16 = (n * 8 + (((k >> 1) + n) & 7)) * 2 + (k & 1);
                H[i16] = *(unsigned short*)&h;
                L[i16] = *(unsigned short*)&l;
            }
        }
    };

    auto compute = [&](int buf) {
        unsigned af[2][2][4], bfr[2][4][2];
#pragma unroll
        for (int s = 0; s < 2; s++) {
            const unsigned* Ab = sA[buf][s];
            const unsigned* Bb = sB[buf][s];
#pragma unroll
            for (int mi = 0; mi < 2; mi++) {
                int r0 = wm + mi * 16 + gr, r1 = r0 + 8;
                af[s][mi][0] = Ab[r0 * 8 + ((tg + r0) & 7)];
                af[s][mi][1] = Ab[r1 * 8 + ((tg + r1) & 7)];
                af[s][mi][2] = Ab[r0 * 8 + ((tg + 4 + r0) & 7)];
                af[s][mi][3] = Ab[r1 * 8 + ((tg + 4 + r1) & 7)];
            }
#pragma unroll
            for (int j = 0; j < 4; j++) {
                int rn = wn + j * 8 + gr;
                bfr[s][j][0] = Bb[rn * 8 + ((tg + rn) & 7)];
                bfr[s][j][1] = Bb[rn * 8 + ((tg + 4 + rn) & 7)];
            }
        }
#pragma unroll
        for (int mi = 0; mi < 2; mi++)
#pragma unroll
            for (int j = 0; j < 4; j++) {
                mma16(acc[mi][j], af[0][mi], bfr[0][j]);   // ah*bh
                mma16(acc[mi][j], af[0][mi], bfr[1][j]);   // ah*bl
                mma16(acc[mi][j], af[1][mi], bfr[0][j]);   // al*bh
            }
    };

    const int nK = Kdim / 16;
    loadG(0);
    storeS(0);
    __syncthreads();
    for (int kt = 0; kt < nK; kt++) {
        int buf = kt & 1;
        bool hasNext = (kt + 1 < nK);
        if (hasNext) loadG((kt + 1) * 16);
        compute(buf);
        if (hasNext) storeS(buf ^ 1);
        __syncthreads();
    }

    if (epi == 0) {
#pragma unroll
        for (int mi = 0; mi < 2; mi++)
#pragma unroll
            for (int half = 0; half < 2; half++) {
                int row = m0 + wm + mi * 16 + half * 8 + gr;
                if (row >= Mrows) continue;
                float* Cr = C + (long)row * Ncols + n0 + wn;
#pragma unroll
                for (int j = 0; j < 4; j++) {
                    int col = j * 8 + tg * 2;
                    float c0 = alpha * acc[mi][j][half * 2 + 0];
                    float c1 = alpha * acc[mi][j][half * 2 + 1];
                    if (accumC) { c0 += Cr[col]; c1 += Cr[col + 1]; }
                    Cr[col] = c0; Cr[col + 1] = c1;
                }
            }
    } else {
        double le = 0.0;
#pragma unroll
        for (int mi = 0; mi < 2; mi++)
#pragma unroll
            for (int half = 0; half < 2; half++) {
                int row = m0 + wm + mi * 16 + half * 8 + gr;
                if (row >= Mrows) continue;
                float* Cr = (epi == 1) ? (C + (long)row * Ncols + n0 + wn) : nullptr;
#pragma unroll
                for (int j = 0; j < 4; j++) {
                    int col = j * 8 + tg * 2;
                    float c0 = acc[mi][j][half * 2 + 0];
                    float c1 = acc[mi][j][half * 2 + 1];
                    float r0 = c0 > 0.f ? c0 : 0.f;
                    float r1 = c1 > 0.f ? c1 : 0.f;
                    le += (double)r0 * (double)r0 + (double)r1 * (double)r1;
                    if (epi == 1) { Cr[col] = r0; Cr[col + 1] = r1; }
                }
            }
        __shared__ double ered[256];
        ered[tid] = le; __syncthreads();
        for (int o = 128; o; o >>= 1) {
            if (tid < o) ered[tid] += ered[tid + o];
            __syncthreads();
        }
        if (tid == 0)
            atomicAdd(e_base + (e_per_z ? blockIdx.z : 0), -0.5 * ered[0]);
    }
}

// ---------------- attention: energy (+optional softmax grads) per (b,h) ----------------
#define ATT_SMEM ((196*65*2 + 196 + 8*200) * 4)

template <bool GRAD>
__global__ void __launch_bounds__(256)
att_kernel(const float* __restrict__ Kall, const float* __restrict__ Qall,
           float* __restrict__ dK, float* __restrict__ dQ,
           double* e_base, int e_per_z) {
    extern __shared__ float sm[];
    const int LD = 65;
    float* Ksh = sm;
    float* Qsh = Ksh + 196 * LD;
    float* lse = Qsh + 196 * LD;
    float* rowbuf = lse + 196;
    __shared__ double wsum[8];

    int bh = blockIdx.x; int b = bh / NH; int h = bh % NH;
    long base = (long)blockIdx.z * NELEM + (long)b * NTOK * DD + h * HD;
    const float* Kg = Kall + base;
    const float* Qg = Qall + base;
    int tid = threadIdx.x, w = tid >> 5, lane = tid & 31;

    for (int i = tid; i < 196 * 16; i += 256) {
        int r = i >> 4, c4 = (i & 15) << 2;
        float4 kv = *(const float4*)(Kg + (long)r * DD + c4);
        float4 qv = *(const float4*)(Qg + (long)r * DD + c4);
        Ksh[r * LD + c4 + 0] = kv.x; Ksh[r * LD + c4 + 1] = kv.y;
        Ksh[r * LD + c4 + 2] = kv.z; Ksh[r * LD + c4 + 3] = kv.w;
        Qsh[r * LD + c4 + 0] = qv.x; Qsh[r * LD + c4 + 1] = qv.y;
        Qsh[r * LD + c4 + 2] = qv.z; Qsh[r * LD + c4 + 3] = qv.w;
    }
    __syncthreads();

    double lsesum = 0.0;
    float* rb = rowbuf + w * 200;

    for (int q = w; q < 196; q += 8) {
        const float* Qr = Qsh + q * LD;
        float mx = -1e30f;
        for (int k = lane; k < 196; k += 32) {
            const float* Kr = Ksh + k * LD;
            float s = 0.f;
#pragma unroll
            for (int y = 0; y < 64; y++) s = fmaf(Kr[y], Qr[y], s);
            s *= BETA;
            rb[k] = s;
            mx = fmaxf(mx, s);
        }
#pragma unroll
        for (int o = 16; o; o >>= 1) mx = fmaxf(mx, __shfl_xor_sync(0xffffffffu, mx, o));
        float se = 0.f;
        for (int k = lane; k < 196; k += 32) {
            float e = expf(rb[k] - mx);
            se += e;
            if (GRAD) rb[k] = e;
        }
#pragma unroll
        for (int o = 16; o; o >>= 1) se += __shfl_xor_sync(0xffffffffu, se, o);
        float l = mx + logf(se);
        if (lane == 0) lsesum += (double)l;
        if (GRAD) {
            if (lane == 0) lse[q] = l;
            float inv = 1.f / se;
            for (int k = lane; k < 196; k += 32) rb[k] *= inv;
            __syncwarp();
            int y0 = lane, y1 = lane + 32;
            float a0 = 0.f, a1 = 0.f;
            for (int k = 0; k < 196; k++) {
                float p = rb[k];
                a0 = fmaf(p, Ksh[k * LD + y0], a0);
                a1 = fmaf(p, Ksh[k * LD + y1], a1);
            }
            long o = (long)(b * NTOK + q) * DD + h * HD;
            dQ[o + y0] = -a0; dQ[o + y1] = -a1;
            __syncwarp();
        }
    }

    if (lane == 0) wsum[w] = lsesum;
    __syncthreads();
    if (tid == 0) {
        double t = 0.0;
        for (int i = 0; i < 8; i++) t += wsum[i];
        atomicAdd(e_base + (e_per_z ? blockIdx.z : 0), -(double)INVB * t);
    }

    if (GRAD) {
        __syncthreads();   // lse[] complete
        for (int k = w; k < 196; k += 8) {
            const float* Kr = Ksh + k * LD;
            for (int q = lane; q < 196; q += 32) {
                const float* Qr = Qsh + q * LD;
                float s = 0.f;
#pragma unroll
                for (int y = 0; y < 64; y++) s = fmaf(Kr[y], Qr[y], s);
                rb[q] = expf(BETA * s - lse[q]);
            }
            __syncwarp();
            int y0 = lane, y1 = lane + 32;
            float a0 = 0.f, a1 = 0.f;
            for (int q = 0; q < 196; q++) {
                float p = rb[q];
                a0 = fmaf(p, Qsh[q * LD + y0], a0);
                a1 = fmaf(p, Qsh[q * LD + y1], a1);
            }
            long o = (long)(b * NTOK + k) * DD + h * HD;
            dK[o + y0] = -a0; dK[o + y1] = -a1;
            __syncwarp();
        }
    }
}

// ---------------- host driver (graph-capturable, no sync, no alloc) ----------------
extern "C" void kernel_launch(void* const* d_in, const int* in_sizes, int n_in,
                              void* d_out, int out_size) {
    const float* x     = (const float*)d_in[0];
    const float* gamma = (const float*)d_in[1];
    const float* delta = (const float*)d_in[2];
    const float* wk    = (const float*)d_in[3];
    const float* wq    = (const float*)d_in[4];
    const float* xi    = (const float*)d_in[5];
    float* out = (float*)d_out;

    float *g, *K, *Q, *h, *dK, *dQ, *dg, *gr, *mean, *rstd;
    double *eref, *ecand;
    cudaGetSymbolAddress((void**)&g,    d_g);
    cudaGetSymbolAddress((void**)&K,    d_K);
    cudaGetSymbolAddress((void**)&Q,    d_Q);
    cudaGetSymbolAddress((void**)&h,    d_h);
    cudaGetSymbolAddress((void**)&dK,   d_dK);
    cudaGetSymbolAddress((void**)&dQ,   d_dQ);
    cudaGetSymbolAddress((void**)&dg,   d_dg);
    cudaGetSymbolAddress((void**)&gr,   d_gr);
    cudaGetSymbolAddress((void**)&mean, d_mean);
    cudaGetSymbolAddress((void**)&rstd, d_rstd);
    cudaGetSymbolAddress((void**)&eref,  d_eref);
    cudaGetSymbolAddress((void**)&ecand, d_ecand);

    cudaFuncSetAttribute(att_kernel<true>,  cudaFuncAttributeMaxDynamicSharedMemorySize, ATT_SMEM);
    cudaFuncSetAttribute(att_kernel<false>, cudaFuncAttributeMaxDynamicSharedMemorySize, ATT_SMEM);

    const long sZ = (long)NELEM;      // per-candidate stride

    zero_kernel<<<1, 32>>>();

    // ---- main pass: forward + gradient at x0 (bf16x3, near-fp32) ----
    ln_fwd_kernel<<<dim3(BN, 1, 1), 256>>>(x, nullptr, g, gamma, delta, mean, rstd, 0);

    dim3 gP(DD / 64, (BN + 127) / 128, 1);           // 12 x 13 = 156
    mma_gemm<1><<<gP, 256>>>(g, wk, K, BN, DD, DD, 1.f, 0, 0, nullptr, 0, 0, 0);
    mma_gemm<1><<<gP, 256>>>(g, wq, Q, BN, DD, DD, 1.f, 0, 0, nullptr, 0, 0, 0);

    att_kernel<true><<<dim3(BB_ * NH, 1, 1), 256, ATT_SMEM>>>(K, Q, dK, dQ, eref, 0);

    dim3 gH(MHOP / 64, (BN + 127) / 128, 1);         // 48 x 13 = 624
    mma_gemm<1><<<gH, 256>>>(g, xi, h, BN, MHOP, DD, 1.f, 0, 1, eref, 0, 0, 0);

    // dg = dK@Wk + dQ@Wq - h@Xi
    mma_gemm<0><<<gP, 256>>>(dK, wk, dg, BN, DD, DD,   1.f, 0, 0, nullptr, 0, 0, 0);
    mma_gemm<0><<<gP, 256>>>(dQ, wq, dg, BN, DD, DD,   1.f, 1, 0, nullptr, 0, 0, 0);
    mma_gemm<0><<<gP, 256>>>(h,  xi, dg, BN, DD, MHOP, -1.f, 1, 0, nullptr, 0, 0, 0);

    ln_bwd_kernel<<<BN, 256>>>(x, mean, rstd, gamma, dg, gr);

    // ---- Armijo: 4 candidates x - lr_k*grad, batched via grid.z ----
    ln_fwd_kernel<<<dim3(BN, 1, 4), 256>>>(x, gr, g, gamma, delta, nullptr, nullptr, 1);

    dim3 gPc(DD / 64, (BN + 127) / 128, 4);
    mma_gemm<1><<<gPc, 256>>>(g, wk, K, BN, DD, DD, 1.f, 0, 0, nullptr, 0, sZ, sZ);
    mma_gemm<1><<<gPc, 256>>>(g, wq, Q, BN, DD, DD, 1.f, 0, 0, nullptr, 0, sZ, sZ);

    att_kernel<false><<<dim3(BB_ * NH, 1, 4), 256, ATT_SMEM>>>(K, Q, nullptr, nullptr, ecand, 1);

    dim3 gHc(MHOP / 64, (BN + 127) / 128, 4);
    mma_gemm<1><<<gHc, 256>>>(g, xi, nullptr, BN, MHOP, DD, 1.f, 0, 2, ecand, 1, sZ, 0);

    select_kernel<<<1, 1>>>();
    update_kernel<<<(NELEM + 255) / 256, 256>>>(x, gr, out);
}

// round 7
// speedup vs baseline: 1.7972x; 1.7972x over previous
#include <cuda_runtime.h>
#include <cuda_bf16.h>
#include <math.h>

// ---------------- problem constants ----------------
#define BB_   8
#define NTOK  196
#define DD    768
#define NH    12
#define HD    64
#define MHOP  3072
#define BN    (BB_*NTOK)          // 1568
#define NELEM (BN*DD)             // 1204224
#define KCAT  4608                // 768 + 768 + 3072
#define BETA  0.125f
#define INVB  8.0f

// ---------------- scratch ----------------
__device__ __align__(256) float d_g  [4L*BN*DD];
__device__ __align__(256) float d_K  [4L*BN*DD];
__device__ __align__(256) float d_Q  [4L*BN*DD];
__device__ __align__(256) float d_Acat[(long)BN*KCAT];   // [dK | dQ | h]
__device__ __align__(256) float d_BT [(long)DD*KCAT];    // [WkT | WqT | -XiT]
__device__ __align__(256) float d_dg [BN*DD];
__device__ __align__(256) float d_gr [BN*DD];
__device__ float  d_mean[BN];
__device__ float  d_rstd[BN];
__device__ double d_eref;
__device__ double d_ecand[4];
__device__ float  d_chosen;
__constant__ float c_lrs[4] = {1.0f, 0.5f, 0.25f, 0.125f};

// ---------------- tiny kernels ----------------
__global__ void zero_kernel() {
    if (threadIdx.x == 0) d_eref = 0.0;
    if (threadIdx.x < 4)  d_ecand[threadIdx.x] = 0.0;
}

__global__ void select_kernel() {
    if (threadIdx.x == 0) {
        double eref = d_eref;
        float chosen = 0.0625f;
        if (d_ecand[3] < eref) chosen = 0.125f;
        if (d_ecand[2] < eref) chosen = 0.25f;
        if (d_ecand[1] < eref) chosen = 0.5f;
        if (d_ecand[0] < eref) chosen = 1.0f;
        d_chosen = chosen;
    }
}

__global__ void update_kernel(const float* __restrict__ x,
                              const float* __restrict__ grad,
                              float* __restrict__ out) {
    int i = blockIdx.x * 256 + threadIdx.x;
    if (i < NELEM) out[i] = x[i] - d_chosen * grad[i];
}

// out[d][colbase + r] = s * in[r][d]; out row stride KCAT, in [R x DD]
__global__ void transpose_kernel(const float* __restrict__ in,
                                 float* __restrict__ outB,
                                 int R, int colbase, float s) {
    __shared__ float t[32][33];
    int d0 = blockIdx.x * 32, r0 = blockIdx.y * 32;
    int tx = threadIdx.x, ty = threadIdx.y;     // 32 x 8
#pragma unroll
    for (int i = 0; i < 4; i++) {
        int r = r0 + ty + i * 8;
        t[ty + i * 8][tx] = in[(long)r * DD + d0 + tx];
    }
    __syncthreads();
#pragma unroll
    for (int i = 0; i < 4; i++) {
        int d = d0 + ty + i * 8;
        outB[(long)d * KCAT + colbase + r0 + tx] = s * t[tx][ty + i * 8];
    }
}

// ---------------- LayerNorm forward ----------------
__global__ void ln_fwd_kernel(const float* __restrict__ x,
                              const float* __restrict__ grad,
                              float* __restrict__ gout,
                              const float* __restrict__ gamma,
                              const float* __restrict__ delta,
                              float* meanOut, float* rstdOut, int useLr) {
    int t = blockIdx.x, z = blockIdx.z, tid = threadIdx.x;
    const float lr = useLr ? c_lrs[z] : 0.f;
    const float* xr = x + (long)t * DD;
    float v[3]; float s = 0.f;
#pragma unroll
    for (int i = 0; i < 3; i++) {
        int c = tid + i * 256;
        float xv = xr[c];
        if (useLr) xv -= lr * grad[(long)t * DD + c];
        v[i] = xv; s += xv;
    }
    __shared__ float red[256];
    red[tid] = s; __syncthreads();
    for (int o = 128; o; o >>= 1) { if (tid < o) red[tid] += red[tid + o]; __syncthreads(); }
    float mu = red[0] * (1.f / DD);
    __syncthreads();
    float s2 = 0.f;
#pragma unroll
    for (int i = 0; i < 3; i++) { float dv = v[i] - mu; s2 += dv * dv; }
    red[tid] = s2; __syncthreads();
    for (int o = 128; o; o >>= 1) { if (tid < o) red[tid] += red[tid + o]; __syncthreads(); }
    float rs = rsqrtf(red[0] * (1.f / DD) + 1e-5f);
    float* orow = gout + (long)z * NELEM + (long)t * DD;
#pragma unroll
    for (int i = 0; i < 3; i++) {
        int c = tid + i * 256;
        orow[c] = gamma[c] * (v[i] - mu) * rs + delta[c];
    }
    if (!useLr && tid == 0) { meanOut[t] = mu; rstdOut[t] = rs; }
}

// ---------------- LayerNorm backward ----------------
__global__ void ln_bwd_kernel(const float* __restrict__ x,
                              const float* __restrict__ mean,
                              const float* __restrict__ rstd,
                              const float* __restrict__ gamma,
                              const float* __restrict__ dgv,
                              float* __restrict__ dx) {
    int t = blockIdx.x, tid = threadIdx.x;
    float mu = mean[t], rs = rstd[t];
    const float* xr = x + (long)t * DD;
    const float* dr = dgv + (long)t * DD;
    float xh[3], dxh[3]; float s1 = 0.f, s2 = 0.f;
#pragma unroll
    for (int i = 0; i < 3; i++) {
        int c = tid + i * 256;
        xh[i]  = (xr[c] - mu) * rs;
        dxh[i] = dr[c] * gamma[c];
        s1 += dxh[i]; s2 += dxh[i] * xh[i];
    }
    __shared__ float r1[256], r2[256];
    r1[tid] = s1; r2[tid] = s2; __syncthreads();
    for (int o = 128; o; o >>= 1) {
        if (tid < o) { r1[tid] += r1[tid + o]; r2[tid] += r2[tid + o]; }
        __syncthreads();
    }
    float m1 = r1[0] * (1.f / DD), m2 = r2[0] * (1.f / DD);
#pragma unroll
    for (int i = 0; i < 3; i++) {
        int c = tid + i * 256;
        dx[(long)t * DD + c] = rs * (dxh[i] - m1 - xh[i] * m2);
    }
}

// ---------------- bf16 split-3 GEMM, 64x64 tile, 128 threads ----------------
// All operands TRANSB=1 style: A[M,K] ld=K, B[N,K] ld=K. Dual-B for fused proj.
// epi: 0 = store alpha*acc ; 1 = relu store + energy ; 2 = energy only
__device__ __forceinline__ void split2(float x, float y, unsigned& hi, unsigned& lo) {
    __nv_bfloat16 hx = __float2bfloat16_rn(x), hy = __float2bfloat16_rn(y);
    __nv_bfloat162 h; h.x = hx; h.y = hy;
    hi = *(unsigned*)&h;
    __nv_bfloat162 l;
    l.x = __float2bfloat16_rn(x - __bfloat162float(hx));
    l.y = __float2bfloat16_rn(y - __bfloat162float(hy));
    lo = *(unsigned*)&l;
}

__device__ __forceinline__ void mma16(float* c, const unsigned* a, const unsigned* b) {
    asm volatile("mma.sync.aligned.m16n8k16.row.col.f32.bf16.bf16.f32 "
                 "{%0,%1,%2,%3}, {%4,%5,%6,%7}, {%8,%9}, {%0,%1,%2,%3};"
                 : "+f"(c[0]), "+f"(c[1]), "+f"(c[2]), "+f"(c[3])
                 : "r"(a[0]), "r"(a[1]), "r"(a[2]), "r"(a[3]),
                   "r"(b[0]), "r"(b[1]));
}

__global__ void __launch_bounds__(128, 4)
gemm64(const float* __restrict__ A,
       const float* __restrict__ B0, const float* __restrict__ B1, int nsplit,
       float* __restrict__ C0, float* __restrict__ C1, int ldC,
       int Mrows, int Kdim, float alpha, int epi,
       double* e_base, int e_per_z, long strideAz, long strideCz) {
    __shared__ unsigned sA[2][2][64 * 8];   // [buf][split][row*8 + swcol]
    __shared__ unsigned sB[2][2][64 * 8];

    const int tid = threadIdx.x;
    const int m0 = blockIdx.y * 64;
    int n0 = blockIdx.x * 64;
    const float* B = B0; float* C = C0;
    if (B1 != nullptr && n0 >= nsplit) { B = B1; C = C1; n0 -= nsplit; }
    A += (long)blockIdx.z * strideAz;
    if (C) C += (long)blockIdx.z * strideCz;

    const int wid = tid >> 5, lane = tid & 31;
    const int wm = (wid >> 1) * 32, wn = (wid & 1) * 32;
    const int gr = lane >> 2, tg = lane & 3;

    float acc[2][4][4];
#pragma unroll
    for (int i = 0; i < 2; i++)
#pragma unroll
        for (int j = 0; j < 4; j++)
#pragma unroll
            for (int t = 0; t < 4; t++) acc[i][j][t] = 0.f;

    float ra[2][4], rb[2][4];

    auto loadG = [&](int k0) {
#pragma unroll
        for (int it = 0; it < 2; it++) {
            int idx = tid + it * 128;
            int r = idx >> 2, c4 = (idx & 3) * 4;
            float4 v = make_float4(0.f, 0.f, 0.f, 0.f);
            if (m0 + r < Mrows)
                v = *(const float4*)(A + (long)(m0 + r) * Kdim + k0 + c4);
            ra[it][0] = v.x; ra[it][1] = v.y; ra[it][2] = v.z; ra[it][3] = v.w;
            float4 w = *(const float4*)(B + (long)(n0 + r) * Kdim + k0 + c4);
            rb[it][0] = w.x; rb[it][1] = w.y; rb[it][2] = w.z; rb[it][3] = w.w;
        }
    };

    auto storeS = [&](int buf) {
#pragma unroll
        for (int it = 0; it < 2; it++) {
            int idx = tid + it * 128;
            int r = idx >> 2, kq = (idx & 3) * 2;
            int b0 = r * 8 + ((kq + r) & 7);
            int b1 = r * 8 + ((kq + 1 + r) & 7);
            unsigned h0, l0, h1, l1;
            split2(ra[it][0], ra[it][1], h0, l0);
            split2(ra[it][2], ra[it][3], h1, l1);
            sA[buf][0][b0] = h0; sA[buf][0][b1] = h1;
            sA[buf][1][b0] = l0; sA[buf][1][b1] = l1;
            split2(rb[it][0], rb[it][1], h0, l0);
            split2(rb[it][2], rb[it][3], h1, l1);
            sB[buf][0][b0] = h0; sB[buf][0][b1] = h1;
            sB[buf][1][b0] = l0; sB[buf][1][b1] = l1;
        }
    };

    auto compute = [&](int buf) {
        unsigned af[2][2][4], bfr[2][4][2];
#pragma unroll
        for (int s = 0; s < 2; s++) {
            const unsigned* Ab = sA[buf][s];
            const unsigned* Bb = sB[buf][s];
#pragma unroll
            for (int mi = 0; mi < 2; mi++) {
                int r0 = wm + mi * 16 + gr, r1 = r0 + 8;
                af[s][mi][0] = Ab[r0 * 8 + ((tg + r0) & 7)];
                af[s][mi][1] = Ab[r1 * 8 + ((tg + r1) & 7)];
                af[s][mi][2] = Ab[r0 * 8 + ((tg + 4 + r0) & 7)];
                af[s][mi][3] = Ab[r1 * 8 + ((tg + 4 + r1) & 7)];
            }
#pragma unroll
            for (int j = 0; j < 4; j++) {
                int rn = wn + j * 8 + gr;
                bfr[s][j][0] = Bb[rn * 8 + ((tg + rn) & 7)];
                bfr[s][j][1] = Bb[rn * 8 + ((tg + 4 + rn) & 7)];
            }
        }
#pragma unroll
        for (int mi = 0; mi < 2; mi++)
#pragma unroll
            for (int j = 0; j < 4; j++) {
                mma16(acc[mi][j], af[0][mi], bfr[0][j]);   // ah*bh
                mma16(acc[mi][j], af[0][mi], bfr[1][j]);   // ah*bl
                mma16(acc[mi][j], af[1][mi], bfr[0][j]);   // al*bh
            }
    };

    const int nK = Kdim / 16;
    loadG(0);
    storeS(0);
    __syncthreads();
    for (int kt = 0; kt < nK; kt++) {
        int buf = kt & 1;
        bool hasNext = (kt + 1 < nK);
        if (hasNext) loadG((kt + 1) * 16);
        compute(buf);
        if (hasNext) storeS(buf ^ 1);
        __syncthreads();
    }

    if (epi == 0) {
#pragma unroll
        for (int mi = 0; mi < 2; mi++)
#pragma unroll
            for (int half = 0; half < 2; half++) {
                int row = m0 + wm + mi * 16 + half * 8 + gr;
                if (row >= Mrows) continue;
                float* Cr = C + (long)row * ldC + n0 + wn;
#pragma unroll
                for (int j = 0; j < 4; j++) {
                    int col = j * 8 + tg * 2;
                    Cr[col]     = alpha * acc[mi][j][half * 2 + 0];
                    Cr[col + 1] = alpha * acc[mi][j][half * 2 + 1];
                }
            }
    } else {
        double le = 0.0;
#pragma unroll
        for (int mi = 0; mi < 2; mi++)
#pragma unroll
            for (int half = 0; half < 2; half++) {
                int row = m0 + wm + mi * 16 + half * 8 + gr;
                if (row >= Mrows) continue;
                float* Cr = (epi == 1) ? (C + (long)row * ldC + n0 + wn) : nullptr;
#pragma unroll
                for (int j = 0; j < 4; j++) {
                    int col = j * 8 + tg * 2;
                    float c0 = acc[mi][j][half * 2 + 0];
                    float c1 = acc[mi][j][half * 2 + 1];
                    float r0 = c0 > 0.f ? c0 : 0.f;
                    float r1 = c1 > 0.f ? c1 : 0.f;
                    le += (double)r0 * (double)r0 + (double)r1 * (double)r1;
                    if (epi == 1) { Cr[col] = r0; Cr[col + 1] = r1; }
                }
            }
        __shared__ double ered[128];
        ered[tid] = le; __syncthreads();
        for (int o = 64; o; o >>= 1) {
            if (tid < o) ered[tid] += ered[tid + o];
            __syncthreads();
        }
        if (tid == 0)
            atomicAdd(e_base + (e_per_z ? blockIdx.z : 0), -0.5 * ered[0]);
    }
}

// ---------------- attention ----------------
#define ATT_LD 68
#define ATT_SMEM ((196*ATT_LD*2 + 196 + 8*200) * 4)

template <bool GRAD>
__global__ void __launch_bounds__(256)
att_kernel(const float* __restrict__ Kall, const float* __restrict__ Qall,
           float* __restrict__ dK, float* __restrict__ dQ, int ldOut,
           double* e_base, int e_per_z) {
    extern __shared__ float sm[];
    const int LD = ATT_LD;
    float* Ksh = sm;
    float* Qsh = Ksh + 196 * LD;
    float* lse = Qsh + 196 * LD;
    float* rowbuf = lse + 196;
    __shared__ double wsum[8];

    int bh = blockIdx.x; int b = bh / NH; int h = bh % NH;
    long base = (long)blockIdx.z * NELEM + (long)b * NTOK * DD + h * HD;
    const float* Kg = Kall + base;
    const float* Qg = Qall + base;
    int tid = threadIdx.x, w = tid >> 5, lane = tid & 31;

    for (int i = tid; i < 196 * 16; i += 256) {
        int r = i >> 4, c4 = (i & 15) << 2;
        float4 kv = *(const float4*)(Kg + (long)r * DD + c4);
        float4 qv = *(const float4*)(Qg + (long)r * DD + c4);
        *(float4*)(Ksh + r * LD + c4) = kv;
        *(float4*)(Qsh + r * LD + c4) = qv;
    }
    __syncthreads();

    double lsesum = 0.0;
    float* rb = rowbuf + w * 200;

    for (int q = w; q < 196; q += 8) {
        const float4* Qr4 = (const float4*)(Qsh + q * LD);
        float mx = -1e30f;
        for (int k = lane; k < 196; k += 32) {
            const float4* Kr4 = (const float4*)(Ksh + k * LD);
            float s = 0.f;
#pragma unroll
            for (int y = 0; y < 16; y++) {
                float4 a = Kr4[y], b4 = Qr4[y];
                s = fmaf(a.x, b4.x, s); s = fmaf(a.y, b4.y, s);
                s = fmaf(a.z, b4.z, s); s = fmaf(a.w, b4.w, s);
            }
            s *= BETA;
            rb[k] = s;
            mx = fmaxf(mx, s);
        }
#pragma unroll
        for (int o = 16; o; o >>= 1) mx = fmaxf(mx, __shfl_xor_sync(0xffffffffu, mx, o));
        float se = 0.f;
        for (int k = lane; k < 196; k += 32) {
            float e = expf(rb[k] - mx);
            se += e;
            if (GRAD) rb[k] = e;
        }
#pragma unroll
        for (int o = 16; o; o >>= 1) se += __shfl_xor_sync(0xffffffffu, se, o);
        float l = mx + logf(se);
        if (lane == 0) lsesum += (double)l;
        if (GRAD) {
            if (lane == 0) lse[q] = l;
            float inv = 1.f / se;
            for (int k = lane; k < 196; k += 32) rb[k] *= inv;
            __syncwarp();
            int y0 = lane, y1 = lane + 32;
            float a0 = 0.f, a1 = 0.f;
            for (int k = 0; k < 196; k++) {
                float p = rb[k];
                a0 = fmaf(p, Ksh[k * LD + y0], a0);
                a1 = fmaf(p, Ksh[k * LD + y1], a1);
            }
            long o = (long)(b * NTOK + q) * ldOut + h * HD;
            dQ[o + y0] = -a0; dQ[o + y1] = -a1;
            __syncwarp();
        }
    }

    if (lane == 0) wsum[w] = lsesum;
    __syncthreads();
    if (tid == 0) {
        double t = 0.0;
        for (int i = 0; i < 8; i++) t += wsum[i];
        atomicAdd(e_base + (e_per_z ? blockIdx.z : 0), -(double)INVB * t);
    }

    if (GRAD) {
        __syncthreads();   // lse[] complete
        for (int k = w; k < 196; k += 8) {
            const float4* Kr4 = (const float4*)(Ksh + k * LD);
            for (int q = lane; q < 196; q += 32) {
                const float4* Qr4 = (const float4*)(Qsh + q * LD);
                float s = 0.f;
#pragma unroll
                for (int y = 0; y < 16; y++) {
                    float4 a = Kr4[y], b4 = Qr4[y];
                    s = fmaf(a.x, b4.x, s); s = fmaf(a.y, b4.y, s);
                    s = fmaf(a.z, b4.z, s); s = fmaf(a.w, b4.w, s);
                }
                rb[q] = expf(BETA * s - lse[q]);
            }
            __syncwarp();
            int y0 = lane, y1 = lane + 32;
            float a0 = 0.f, a1 = 0.f;
            for (int q = 0; q < 196; q++) {
                float p = rb[q];
                a0 = fmaf(p, Qsh[q * LD + y0], a0);
                a1 = fmaf(p, Qsh[q * LD + y1], a1);
            }
            long o = (long)(b * NTOK + k) * ldOut + h * HD;
            dK[o + y0] = -a0; dK[o + y1] = -a1;
            __syncwarp();
        }
    }
}

// ---------------- host driver ----------------
extern "C" void kernel_launch(void* const* d_in, const int* in_sizes, int n_in,
                              void* d_out, int out_size) {
    const float* x     = (const float*)d_in[0];
    const float* gamma = (const float*)d_in[1];
    const float* delta = (const float*)d_in[2];
    const float* wk    = (const float*)d_in[3];
    const float* wq    = (const float*)d_in[4];
    const float* xi    = (const float*)d_in[5];
    float* out = (float*)d_out;

    float *g, *K, *Q, *Acat, *BT, *dg, *gr, *mean, *rstd;
    double *eref, *ecand;
    cudaGetSymbolAddress((void**)&g,    d_g);
    cudaGetSymbolAddress((void**)&K,    d_K);
    cudaGetSymbolAddress((void**)&Q,    d_Q);
    cudaGetSymbolAddress((void**)&Acat, d_Acat);
    cudaGetSymbolAddress((void**)&BT,   d_BT);
    cudaGetSymbolAddress((void**)&dg,   d_dg);
    cudaGetSymbolAddress((void**)&gr,   d_gr);
    cudaGetSymbolAddress((void**)&mean, d_mean);
    cudaGetSymbolAddress((void**)&rstd, d_rstd);
    cudaGetSymbolAddress((void**)&eref,  d_eref);
    cudaGetSymbolAddress((void**)&ecand, d_ecand);

    cudaFuncSetAttribute(att_kernel<true>,  cudaFuncAttributeMaxDynamicSharedMemorySize, ATT_SMEM);
    cudaFuncSetAttribute(att_kernel<false>, cudaFuncAttributeMaxDynamicSharedMemorySize, ATT_SMEM);

    const long sZ = (long)NELEM;
    const int MB = (BN + 63) / 64;     // 25

    zero_kernel<<<1, 32>>>();

    // pack BT = [WkT | WqT | -XiT]  (768 x 4608)
    transpose_kernel<<<dim3(DD / 32, DD / 32), dim3(32, 8)>>>(wk, BT, DD, 0, 1.f);
    transpose_kernel<<<dim3(DD / 32, DD / 32), dim3(32, 8)>>>(wq, BT, DD, DD, 1.f);
    transpose_kernel<<<dim3(DD / 32, MHOP / 32), dim3(32, 8)>>>(xi, BT, MHOP, 2 * DD, -1.f);

    // ---- main pass ----
    ln_fwd_kernel<<<dim3(BN, 1, 1), 256>>>(x, nullptr, g, gamma, delta, mean, rstd, 0);

    // fused K/Q projection: N = 1536
    gemm64<<<dim3(2 * DD / 64, MB), 128>>>(g, wk, wq, DD, K, Q, DD,
                                           BN, DD, 1.f, 0, nullptr, 0, 0, 0);

    att_kernel<true><<<dim3(BB_ * NH, 1, 1), 256, ATT_SMEM>>>(
        K, Q, Acat, Acat + DD, KCAT, eref, 0);

    // Hopfield fwd: relu store into Acat[:,1536:4608] + energy
    gemm64<<<dim3(MHOP / 64, MB), 128>>>(g, xi, nullptr, 0, Acat + 2 * DD, nullptr, KCAT,
                                         BN, DD, 1.f, 1, eref, 0, 0, 0);

    // fused dgrad: dg = Acat @ BT^T   (K = 4608)
    gemm64<<<dim3(DD / 64, MB), 128>>>(Acat, BT, nullptr, 0, dg, nullptr, DD,
                                       BN, KCAT, 1.f, 0, nullptr, 0, 0, 0);

    ln_bwd_kernel<<<BN, 256>>>(x, mean, rstd, gamma, dg, gr);

    // ---- Armijo candidates (z = 4) ----
    ln_fwd_kernel<<<dim3(BN, 1, 4), 256>>>(x, gr, g, gamma, delta, nullptr, nullptr, 1);

    gemm64<<<dim3(2 * DD / 64, MB, 4), 128>>>(g, wk, wq, DD, K, Q, DD,
                                              BN, DD, 1.f, 0, nullptr, 0, sZ, sZ);

    att_kernel<false><<<dim3(BB_ * NH, 1, 4), 256, ATT_SMEM>>>(
        K, Q, nullptr, nullptr, 0, ecand, 1);

    gemm64<<<dim3(MHOP / 64, MB, 4), 128>>>(g, xi, nullptr, 0, nullptr, nullptr, 0,
                                            BN, DD, 1.f, 2, ecand, 1, sZ, 0);

    select_kernel<<<1, 1>>>();
    update_kernel<<<(NELEM + 255) / 256, 256>>>(x, gr, out);
}

// round 9
// speedup vs baseline: 2.0548x; 1.1433x over previous
#include <cuda_runtime.h>
#include <cuda_bf16.h>
#include <math.h>

// ---------------- problem constants ----------------
#define BB_   8
#define NTOK  196
#define DD    768
#define NH    12
#define HD    64
#define MHOP  3072
#define BN    (BB_*NTOK)          // 1568
#define NELEM (BN*DD)             // 1204224
#define KCAT  4608                // 768 + 768 + 3072
#define BETA  0.125f
#define INVB  8.0f

// ---------------- scratch ----------------
__device__ __align__(256) float d_g  [4L*BN*DD];
__device__ __align__(256) float d_K  [4L*BN*DD];
__device__ __align__(256) float d_Q  [4L*BN*DD];
__device__ __align__(256) float d_Acat[(long)BN*KCAT];   // [dK | dQ | h]
__device__ __align__(256) float d_BT [(long)DD*KCAT];    // [WkT | WqT | -XiT]
__device__ __align__(256) float d_dg [BN*DD];
__device__ __align__(256) float d_gr [BN*DD];
__device__ float  d_mean[BN];
__device__ float  d_rstd[BN];
__device__ double d_eref;
__device__ double d_ecand[4];
__device__ float  d_chosen;
__constant__ float c_lrs[4] = {1.0f, 0.5f, 0.25f, 0.125f};

// ---------------- tiny kernels ----------------
__global__ void zero_kernel() {
    if (threadIdx.x == 0) d_eref = 0.0;
    if (threadIdx.x < 4)  d_ecand[threadIdx.x] = 0.0;
}

__global__ void select_kernel() {
    if (threadIdx.x == 0) {
        double eref = d_eref;
        float chosen = 0.0625f;
        if (d_ecand[3] < eref) chosen = 0.125f;
        if (d_ecand[2] < eref) chosen = 0.25f;
        if (d_ecand[1] < eref) chosen = 0.5f;
        if (d_ecand[0] < eref) chosen = 1.0f;
        d_chosen = chosen;
    }
}

__global__ void update_kernel(const float* __restrict__ x,
                              const float* __restrict__ grad,
                              float* __restrict__ out) {
    int i = blockIdx.x * 256 + threadIdx.x;
    if (i < NELEM) out[i] = x[i] - d_chosen * grad[i];
}

// out[d][colbase + r] = s * in[r][d]
__global__ void transpose_kernel(const float* __restrict__ in,
                                 float* __restrict__ outB,
                                 int R, int colbase, float s) {
    __shared__ float t[32][33];
    int d0 = blockIdx.x * 32, r0 = blockIdx.y * 32;
    int tx = threadIdx.x, ty = threadIdx.y;     // 32 x 8
#pragma unroll
    for (int i = 0; i < 4; i++) {
        int r = r0 + ty + i * 8;
        t[ty + i * 8][tx] = in[(long)r * DD + d0 + tx];
    }
    __syncthreads();
#pragma unroll
    for (int i = 0; i < 4; i++) {
        int d = d0 + ty + i * 8;
        outB[(long)d * KCAT + colbase + r0 + tx] = s * t[tx][ty + i * 8];
    }
}

// ---------------- LayerNorm forward ----------------
__global__ void ln_fwd_kernel(const float* __restrict__ x,
                              const float* __restrict__ grad,
                              float* __restrict__ gout,
                              const float* __restrict__ gamma,
                              const float* __restrict__ delta,
                              float* meanOut, float* rstdOut, int useLr) {
    int t = blockIdx.x, z = blockIdx.z, tid = threadIdx.x;
    const float lr = useLr ? c_lrs[z] : 0.f;
    const float* xr = x + (long)t * DD;
    float v[3]; float s = 0.f;
#pragma unroll
    for (int i = 0; i < 3; i++) {
        int c = tid + i * 256;
        float xv = xr[c];
        if (useLr) xv -= lr * grad[(long)t * DD + c];
        v[i] = xv; s += xv;
    }
    __shared__ float red[256];
    red[tid] = s; __syncthreads();
    for (int o = 128; o; o >>= 1) { if (tid < o) red[tid] += red[tid + o]; __syncthreads(); }
    float mu = red[0] * (1.f / DD);
    __syncthreads();
    float s2 = 0.f;
#pragma unroll
    for (int i = 0; i < 3; i++) { float dv = v[i] - mu; s2 += dv * dv; }
    red[tid] = s2; __syncthreads();
    for (int o = 128; o; o >>= 1) { if (tid < o) red[tid] += red[tid + o]; __syncthreads(); }
    float rs = rsqrtf(red[0] * (1.f / DD) + 1e-5f);
    float* orow = gout + (long)z * NELEM + (long)t * DD;
#pragma unroll
    for (int i = 0; i < 3; i++) {
        int c = tid + i * 256;
        orow[c] = gamma[c] * (v[i] - mu) * rs + delta[c];
    }
    if (!useLr && tid == 0) { meanOut[t] = mu; rstdOut[t] = rs; }
}

// ---------------- LayerNorm backward ----------------
__global__ void ln_bwd_kernel(const float* __restrict__ x,
                              const float* __restrict__ mean,
                              const float* __restrict__ rstd,
                              const float* __restrict__ gamma,
                              const float* __restrict__ dgv,
                              float* __restrict__ dx) {
    int t = blockIdx.x, tid = threadIdx.x;
    float mu = mean[t], rs = rstd[t];
    const float* xr = x + (long)t * DD;
    const float* dr = dgv + (long)t * DD;
    float xh[3], dxh[3]; float s1 = 0.f, s2 = 0.f;
#pragma unroll
    for (int i = 0; i < 3; i++) {
        int c = tid + i * 256;
        xh[i]  = (xr[c] - mu) * rs;
        dxh[i] = dr[c] * gamma[c];
        s1 += dxh[i]; s2 += dxh[i] * xh[i];
    }
    __shared__ float r1[256], r2[256];
    r1[tid] = s1; r2[tid] = s2; __syncthreads();
    for (int o = 128; o; o >>= 1) {
        if (tid < o) { r1[tid] += r1[tid + o]; r2[tid] += r2[tid + o]; }
        __syncthreads();
    }
    float m1 = r1[0] * (1.f / DD), m2 = r2[0] * (1.f / DD);
#pragma unroll
    for (int i = 0; i < 3; i++) {
        int c = tid + i * 256;
        dx[(long)t * DD + c] = rs * (dxh[i] - m1 - xh[i] * m2);
    }
}

// ---------------- bf16 tensor-core GEMM, 64x64 tile, 128 threads ----------------
// NTERM=3: split hi/lo, 3 MMA products (near-fp32). NTERM=1: single bf16 pass.
// FUSED=1: N=4608 multi-target -- B chosen among {wk, wq, xi} per 64-col tile,
//          C among {CK, CQ, CH}; xi-region epilogue = epiH (1 relu+energy, 2 energy).
// FUSED=0: plain single-B (dgrad).  All B operands are [N,K] row-major.
__device__ __forceinline__ void split2(float x, float y, unsigned& hi, unsigned& lo) {
    __nv_bfloat16 hx = __float2bfloat16_rn(x), hy = __float2bfloat16_rn(y);
    __nv_bfloat162 h; h.x = hx; h.y = hy;
    hi = *(unsigned*)&h;
    __nv_bfloat162 l;
    l.x = __float2bfloat16_rn(x - __bfloat162float(hx));
    l.y = __float2bfloat16_rn(y - __bfloat162float(hy));
    lo = *(unsigned*)&l;
}

__device__ __forceinline__ void pack2(float x, float y, unsigned& hi) {
    __nv_bfloat162 h; h.x = __float2bfloat16_rn(x); h.y = __float2bfloat16_rn(y);
    hi = *(unsigned*)&h;
}

__device__ __forceinline__ void mma16(float* c, const unsigned* a, const unsigned* b) {
    asm volatile("mma.sync.aligned.m16n8k16.row.col.f32.bf16.bf16.f32 "
                 "{%0,%1,%2,%3}, {%4,%5,%6,%7}, {%8,%9}, {%0,%1,%2,%3};"
                 : "+f"(c[0]), "+f"(c[1]), "+f"(c[2]), "+f"(c[3])
                 : "r"(a[0]), "r"(a[1]), "r"(a[2]), "r"(a[3]),
                   "r"(b[0]), "r"(b[1]));
}

template <int NTERM, int FUSED>
__global__ void __launch_bounds__(128, 4)
gemm_k(const float* __restrict__ A,
       const float* __restrict__ B0, const float* __restrict__ B1,
       const float* __restrict__ B2,
       float* __restrict__ C0, float* __restrict__ C1, float* __restrict__ C2,
       int ldC01, int ldC2,
       int Mrows, int Kdim, int epiH,
       double* e_base, int e_per_z, long strideAz, long strideCz) {
    constexpr int NS = (NTERM == 3) ? 2 : 1;
    __shared__ unsigned sA[2][NS][64 * 8];
    __shared__ unsigned sB[2][NS][64 * 8];

    const int tid = threadIdx.x;
    const int m0 = blockIdx.y * 64;
    const int n0 = blockIdx.x * 64;

    const float* B; float* C; int ldC, epi, ncol;
    if (FUSED) {
        if (n0 < DD)            { B = B0 + (long)n0 * Kdim;            C = C0; ncol = n0;       ldC = ldC01; epi = 0; }
        else if (n0 < 2 * DD)   { B = B1 + (long)(n0 - DD) * Kdim;     C = C1; ncol = n0 - DD;  ldC = ldC01; epi = 0; }
        else                    { B = B2 + (long)(n0 - 2 * DD) * Kdim; C = C2; ncol = n0;       ldC = ldC2;  epi = epiH; }
    } else {
        B = B0 + (long)n0 * Kdim; C = C0; ncol = n0; ldC = ldC01; epi = epiH;
    }
    A += (long)blockIdx.z * strideAz;
    if (C != nullptr) C += (long)blockIdx.z * strideCz;

    const int wid = tid >> 5, lane = tid & 31;
    const int wm = (wid >> 1) * 32, wn = (wid & 1) * 32;
    const int gr = lane >> 2, tg = lane & 3;

    float acc[2][4][4];
#pragma unroll
    for (int i = 0; i < 2; i++)
#pragma unroll
        for (int j = 0; j < 4; j++)
#pragma unroll
            for (int t = 0; t < 4; t++) acc[i][j][t] = 0.f;

    float ra[2][4], rb[2][4];

    auto loadG = [&](int k0) {
#pragma unroll
        for (int it = 0; it < 2; it++) {
            int idx = tid + it * 128;
            int r = idx >> 2, c4 = (idx & 3) * 4;
            float4 v = make_float4(0.f, 0.f, 0.f, 0.f);
            if (m0 + r < Mrows)
                v = *(const float4*)(A + (long)(m0 + r) * Kdim + k0 + c4);
            ra[it][0] = v.x; ra[it][1] = v.y; ra[it][2] = v.z; ra[it][3] = v.w;
            float4 w = *(const float4*)(B + (long)r * Kdim + k0 + c4);
            rb[it][0] = w.x; rb[it][1] = w.y; rb[it][2] = w.z; rb[it][3] = w.w;
        }
    };

    auto storeS = [&](int buf) {
#pragma unroll
        for (int it = 0; it < 2; it++) {
            int idx = tid + it * 128;
            int r = idx >> 2, kq = (idx & 3) * 2;
            int b0 = r * 8 + ((kq + r) & 7);
            int b1 = r * 8 + ((kq + 1 + r) & 7);
            if (NS == 2) {
                unsigned h0, l0, h1, l1;
                split2(ra[it][0], ra[it][1], h0, l0);
                split2(ra[it][2], ra[it][3], h1, l1);
                sA[buf][0][b0] = h0; sA[buf][0][b1] = h1;
                sA[buf][NS - 1][b0] = l0; sA[buf][NS - 1][b1] = l1;
                split2(rb[it][0], rb[it][1], h0, l0);
                split2(rb[it][2], rb[it][3], h1, l1);
                sB[buf][0][b0] = h0; sB[buf][0][b1] = h1;
                sB[buf][NS - 1][b0] = l0; sB[buf][NS - 1][b1] = l1;
            } else {
                unsigned h0, h1;
                pack2(ra[it][0], ra[it][1], h0);
                pack2(ra[it][2], ra[it][3], h1);
                sA[buf][0][b0] = h0; sA[buf][0][b1] = h1;
                pack2(rb[it][0], rb[it][1], h0);
                pack2(rb[it][2], rb[it][3], h1);
                sB[buf][0][b0] = h0; sB[buf][0][b1] = h1;
            }
        }
    };

    auto compute = [&](int buf) {
        unsigned af[NS][2][4], bfr[NS][4][2];
#pragma unroll
        for (int s = 0; s < NS; s++) {
            const unsigned* Ab = sA[buf][s];
            const unsigned* Bb = sB[buf][s];
#pragma unroll
            for (int mi = 0; mi < 2; mi++) {
                int r0 = wm + mi * 16 + gr, r1 = r0 + 8;
                af[s][mi][0] = Ab[r0 * 8 + ((tg + r0) & 7)];
                af[s][mi][1] = Ab[r1 * 8 + ((tg + r1) & 7)];
                af[s][mi][2] = Ab[r0 * 8 + ((tg + 4 + r0) & 7)];
                af[s][mi][3] = Ab[r1 * 8 + ((tg + 4 + r1) & 7)];
            }
#pragma unroll
            for (int j = 0; j < 4; j++) {
                int rn = wn + j * 8 + gr;
                bfr[s][j][0] = Bb[rn * 8 + ((tg + rn) & 7)];
                bfr[s][j][1] = Bb[rn * 8 + ((tg + 4 + rn) & 7)];
            }
        }
#pragma unroll
        for (int mi = 0; mi < 2; mi++)
#pragma unroll
            for (int j = 0; j < 4; j++) {
                mma16(acc[mi][j], af[0][mi], bfr[0][j]);       // ah*bh
                if (NS == 2) {
                    mma16(acc[mi][j], af[0][mi], bfr[1][j]);   // ah*bl
                    mma16(acc[mi][j], af[1][mi], bfr[0][j]);   // al*bh
                }
            }
    };

    const int nK = Kdim / 16;
    loadG(0);
    storeS(0);
    __syncthreads();
    for (int kt = 0; kt < nK; kt++) {
        int buf = kt & 1;
        bool hasNext = (kt + 1 < nK);
        if (hasNext) loadG((kt + 1) * 16);
        compute(buf);
        if (hasNext) storeS(buf ^ 1);
        __syncthreads();
    }

    if (epi == 0) {
#pragma unroll
        for (int mi = 0; mi < 2; mi++)
#pragma unroll
            for (int half = 0; half < 2; half++) {
                int row = m0 + wm + mi * 16 + half * 8 + gr;
                if (row >= Mrows) continue;
                float* Cr = C + (long)row * ldC + ncol + wn;
#pragma unroll
                for (int j = 0; j < 4; j++) {
                    int col = j * 8 + tg * 2;
                    Cr[col]     = acc[mi][j][half * 2 + 0];
                    Cr[col + 1] = acc[mi][j][half * 2 + 1];
                }
            }
    } else {
        double le = 0.0;
#pragma unroll
        for (int mi = 0; mi < 2; mi++)
#pragma unroll
            for (int half = 0; half < 2; half++) {
                int row = m0 + wm + mi * 16 + half * 8 + gr;
                if (row >= Mrows) continue;
                float* Cr = (epi == 1) ? (C + (long)row * ldC + ncol + wn) : nullptr;
#pragma unroll
                for (int j = 0; j < 4; j++) {
                    int col = j * 8 + tg * 2;
                    float c0 = acc[mi][j][half * 2 + 0];
                    float c1 = acc[mi][j][half * 2 + 1];
                    float r0 = c0 > 0.f ? c0 : 0.f;
                    float r1 = c1 > 0.f ? c1 : 0.f;
                    le += (double)r0 * (double)r0 + (double)r1 * (double)r1;
                    if (epi == 1) { Cr[col] = r0; Cr[col + 1] = r1; }
                }
            }
        __shared__ double ered[128];
        ered[tid] = le; __syncthreads();
        for (int o = 64; o; o >>= 1) {
            if (tid < o) ered[tid] += ered[tid + o];
            __syncthreads();
        }
        if (tid == 0)
            atomicAdd(e_base + (e_per_z ? blockIdx.z : 0), -0.5 * ered[0]);
    }
}

// ---------------- attention ----------------
#define ATT_LD 68
#define ATT_SMEM ((196*ATT_LD*2 + 196 + 8*200) * 4)

template <bool GRAD>
__global__ void __launch_bounds__(256)
att_kernel(const float* __restrict__ Kall, const float* __restrict__ Qall,
           float* __restrict__ dK, float* __restrict__ dQ, int ldOut,
           double* e_base, int e_per_z) {
    extern __shared__ float sm[];
    const int LD = ATT_LD;
    float* Ksh = sm;
    float* Qsh = Ksh + 196 * LD;
    float* lse = Qsh + 196 * LD;
    float* rowbuf = lse + 196;
    __shared__ double wsum[8];

    int bh = blockIdx.x; int b = bh / NH; int h = bh % NH;
    long base = (long)blockIdx.z * NELEM + (long)b * NTOK * DD + h * HD;
    const float* Kg = Kall + base;
    const float* Qg = Qall + base;
    int tid = threadIdx.x, w = tid >> 5, lane = tid & 31;

    for (int i = tid; i < 196 * 16; i += 256) {
        int r = i >> 4, c4 = (i & 15) << 2;
        float4 kv = *(const float4*)(Kg + (long)r * DD + c4);
        float4 qv = *(const float4*)(Qg + (long)r * DD + c4);
        *(float4*)(Ksh + r * LD + c4) = kv;
        *(float4*)(Qsh + r * LD + c4) = qv;
    }
    __syncthreads();

    double lsesum = 0.0;
    float* rb = rowbuf + w * 200;

    for (int q = w; q < 196; q += 8) {
        const float4* Qr4 = (const float4*)(Qsh + q * LD);
        float mx = -1e30f;
        for (int k = lane; k < 196; k += 32) {
            const float4* Kr4 = (const float4*)(Ksh + k * LD);
            float s = 0.f;
#pragma unroll
            for (int y = 0; y < 16; y++) {
                float4 a = Kr4[y], b4 = Qr4[y];
                s = fmaf(a.x, b4.x, s); s = fmaf(a.y, b4.y, s);
                s = fmaf(a.z, b4.z, s); s = fmaf(a.w, b4.w, s);
            }
            s *= BETA;
            rb[k] = s;
            mx = fmaxf(mx, s);
        }
#pragma unroll
        for (int o = 16; o; o >>= 1) mx = fmaxf(mx, __shfl_xor_sync(0xffffffffu, mx, o));
        float se = 0.f;
        for (int k = lane; k < 196; k += 32) {
            float e = expf(rb[k] - mx);
            se += e;
            if (GRAD) rb[k] = e;
        }
#pragma unroll
        for (int o = 16; o; o >>= 1) se += __shfl_xor_sync(0xffffffffu, se, o);
        float l = mx + logf(se);
        if (lane == 0) lsesum += (double)l;
        if (GRAD) {
            if (lane == 0) lse[q] = l;
            float inv = 1.f / se;
            for (int k = lane; k < 196; k += 32) rb[k] *= inv;
            __syncwarp();
            int y0 = lane, y1 = lane + 32;
            float a0 = 0.f, a1 = 0.f;
            for (int k = 0; k < 196; k++) {
                float p = rb[k];
                a0 = fmaf(p, Ksh[k * LD + y0], a0);
                a1 = fmaf(p, Ksh[k * LD + y1], a1);
            }
            long o = (long)(b * NTOK + q) * ldOut + h * HD;
            dQ[o + y0] = -a0; dQ[o + y1] = -a1;
            __syncwarp();
        }
    }

    if (lane == 0) wsum[w] = lsesum;
    __syncthreads();
    if (tid == 0) {
        double t = 0.0;
        for (int i = 0; i < 8; i++) t += wsum[i];
        atomicAdd(e_base + (e_per_z ? blockIdx.z : 0), -(double)INVB * t);
    }

    if (GRAD) {
        __syncthreads();   // lse[] complete
        for (int k = w; k < 196; k += 8) {
            const float4* Kr4 = (const float4*)(Ksh + k * LD);
            for (int q = lane; q < 196; q += 32) {
                const float4* Qr4 = (const float4*)(Qsh + q * LD);
                float s = 0.f;
#pragma unroll
                for (int y = 0; y < 16; y++) {
                    float4 a = Kr4[y], b4 = Qr4[y];
                    s = fmaf(a.x, b4.x, s); s = fmaf(a.y, b4.y, s);
                    s = fmaf(a.z, b4.z, s); s = fmaf(a.w, b4.w, s);
                }
                rb[q] = expf(BETA * s - lse[q]);
            }
            __syncwarp();
            int y0 = lane, y1 = lane + 32;
            float a0 = 0.f, a1 = 0.f;
            for (int q = 0; q < 196; q++) {
                float p = rb[q];
                a0 = fmaf(p, Qsh[q * LD + y0], a0);
                a1 = fmaf(p, Qsh[q * LD + y1], a1);
            }
            long o = (long)(b * NTOK + k) * ldOut + h * HD;
            dK[o + y0] = -a0; dK[o + y1] = -a1;
            __syncwarp();
        }
    }
}

// ---------------- host driver ----------------
extern "C" void kernel_launch(void* const* d_in, const int* in_sizes, int n_in,
                              void* d_out, int out_size) {
    const float* x     = (const float*)d_in[0];
    const float* gamma = (const float*)d_in[1];
    const float* delta = (const float*)d_in[2];
    const float* wk    = (const float*)d_in[3];
    const float* wq    = (const float*)d_in[4];
    const float* xi    = (const float*)d_in[5];
    float* out = (float*)d_out;

    float *g, *K, *Q, *Acat, *BT, *dg, *gr, *mean, *rstd;
    double *eref, *ecand;
    cudaGetSymbolAddress((void**)&g,    d_g);
    cudaGetSymbolAddress((void**)&K,    d_K);
    cudaGetSymbolAddress((void**)&Q,    d_Q);
    cudaGetSymbolAddress((void**)&Acat, d_Acat);
    cudaGetSymbolAddress((void**)&BT,   d_BT);
    cudaGetSymbolAddress((void**)&dg,   d_dg);
    cudaGetSymbolAddress((void**)&gr,   d_gr);
    cudaGetSymbolAddress((void**)&mean, d_mean);
    cudaGetSymbolAddress((void**)&rstd, d_rstd);
    cudaGetSymbolAddress((void**)&eref,  d_eref);
    cudaGetSymbolAddress((void**)&ecand, d_ecand);

    cudaFuncSetAttribute(att_kernel<true>,  cudaFuncAttributeMaxDynamicSharedMemorySize, ATT_SMEM);
    cudaFuncSetAttribute(att_kernel<false>, cudaFuncAttributeMaxDynamicSharedMemorySize, ATT_SMEM);

    const long sZ = (long)NELEM;
    const int MB = (BN + 63) / 64;     // 25

    zero_kernel<<<1, 32>>>();

    // pack BT = [WkT | WqT | -XiT]  (768 x 4608) for the fused dgrad
    transpose_kernel<<<dim3(DD / 32, DD / 32), dim3(32, 8)>>>(wk, BT, DD, 0, 1.f);
    transpose_kernel<<<dim3(DD / 32, DD / 32), dim3(32, 8)>>>(wq, BT, DD, DD, 1.f);
    transpose_kernel<<<dim3(DD / 32, MHOP / 32), dim3(32, 8)>>>(xi, BT, MHOP, 2 * DD, -1.f);

    // ---- main pass (split-3 bf16, near-fp32) ----
    ln_fwd_kernel<<<dim3(BN, 1, 1), 256>>>(x, nullptr, g, gamma, delta, mean, rstd, 0);

    // fused K/Q/h: N = 4608, one launch. h -> relu store into Acat + energy(eref)
    gemm_k<3, 1><<<dim3(KCAT / 64, MB), 128>>>(
        g, wk, wq, xi, K, Q, Acat, DD, KCAT,
        BN, DD, /*epiH=*/1, eref, 0, 0, 0);

    att_kernel<true><<<dim3(BB_ * NH, 1, 1), 256, ATT_SMEM>>>(
        K, Q, Acat, Acat + DD, KCAT, eref, 0);

    // fused dgrad: dg = Acat @ BT^T   (K = 4608)
    gemm_k<3, 0><<<dim3(DD / 64, MB), 128>>>(
        Acat, BT, nullptr, nullptr, dg, nullptr, nullptr, DD, 0,
        BN, KCAT, /*epiH=*/0, nullptr, 0, 0, 0);

    ln_bwd_kernel<<<BN, 256>>>(x, mean, rstd, gamma, dg, gr);

    // ---- Armijo candidates (z = 4): single-pass bf16, energies only ----
    ln_fwd_kernel<<<dim3(BN, 1, 4), 256>>>(x, gr, g, gamma, delta, nullptr, nullptr, 1);

    gemm_k<1, 1><<<dim3(KCAT / 64, MB, 4), 128>>>(
        g, wk, wq, xi, K, Q, nullptr, DD, 0,
        BN, DD, /*epiH=*/2, ecand, 1, sZ, sZ);

    att_kernel<false><<<dim3(BB_ * NH, 1, 4), 256, ATT_SMEM>>>(
        K, Q, nullptr, nullptr, 0, ecand, 1);

    select_kernel<<<1, 1>>>();
    update_kernel<<<(NELEM + 255) / 256, 256>>>(x, gr, out);
}

// round 11
// speedup vs baseline: 2.1393x; 1.0411x over previous
#include <cuda_runtime.h>
#include <cuda_bf16.h>
#include <math.h>

// ---------------- problem constants ----------------
#define BB_   8
#define NTOK  196
#define DD    768
#define NH    12
#define HD    64
#define MHOP  3072
#define BN    (BB_*NTOK)          // 1568
#define NELEM (BN*DD)             // 1204224
#define KCAT  4608                // 768 + 768 + 3072
#define BETA  0.125f
#define INVB  8.0f

typedef __nv_bfloat16 bf16;

// ---------------- scratch ----------------
__device__ __align__(256) bf16  d_ghi[4L*BN*DD];
__device__ __align__(256) bf16  d_glo[(long)BN*DD];
__device__ __align__(256) float d_K  [4L*BN*DD];
__device__ __align__(256) float d_Q  [4L*BN*DD];
__device__ __align__(256) bf16  d_Ahi[(long)BN*KCAT];    // [dK | dQ | h] hi
__device__ __align__(256) bf16  d_Alo[(long)BN*KCAT];    // lo
__device__ __align__(256) bf16  d_whi[(long)KCAT*DD];    // [wk|wq|xi] hi
__device__ __align__(256) bf16  d_wlo[(long)KCAT*DD];
__device__ __align__(256) bf16  d_BThi[(long)DD*KCAT];   // [WkT|WqT|-XiT] hi
__device__ __align__(256) bf16  d_BTlo[(long)DD*KCAT];
__device__ __align__(256) float d_dg [BN*DD];
__device__ __align__(256) float d_gr [BN*DD];
__device__ float  d_mean[BN];
__device__ float  d_rstd[BN];
__device__ double d_eref;
__device__ double d_ecand[4];
__device__ float  d_chosen;
__constant__ float c_lrs[4] = {1.0f, 0.5f, 0.25f, 0.125f};

// ---------------- helpers ----------------
__device__ __forceinline__ void hsplit(float v, bf16& h, bf16& l) {
    h = __float2bfloat16_rn(v);
    l = __float2bfloat16_rn(v - __bfloat162float(h));
}

// ---------------- tiny kernels ----------------
__global__ void zero_kernel() {
    if (threadIdx.x == 0) d_eref = 0.0;
    if (threadIdx.x < 4)  d_ecand[threadIdx.x] = 0.0;
}

__global__ void select_kernel() {
    if (threadIdx.x == 0) {
        double eref = d_eref;
        float chosen = 0.0625f;
        if (d_ecand[3] < eref) chosen = 0.125f;
        if (d_ecand[2] < eref) chosen = 0.25f;
        if (d_ecand[1] < eref) chosen = 0.5f;
        if (d_ecand[0] < eref) chosen = 1.0f;
        d_chosen = chosen;
    }
}

__global__ void update_kernel(const float* __restrict__ x,
                              const float* __restrict__ grad,
                              float* __restrict__ out) {
    int i = blockIdx.x * 256 + threadIdx.x;
    if (i < NELEM) out[i] = x[i] - d_chosen * grad[i];
}

// weights -> concat bf16 hi/lo  [4608][768]
__global__ void w2bf_kernel(const float* __restrict__ wk,
                            const float* __restrict__ wq,
                            const float* __restrict__ xi,
                            bf16* __restrict__ whi, bf16* __restrict__ wlo) {
    long i = (long)blockIdx.x * 256 + threadIdx.x;
    if (i >= (long)KCAT * DD) return;
    long n = i / DD;
    float v;
    if (n < DD)           v = wk[i];
    else if (n < 2 * DD)  v = wq[i - (long)DD * DD];
    else                  v = xi[i - 2L * DD * DD];
    bf16 h, l; hsplit(v, h, l);
    whi[i] = h; wlo[i] = l;
}

// outHi/Lo[d][colbase + r] = hi/lo(s * in[r][d]);   out row stride KCAT
__global__ void btprep_kernel(const float* __restrict__ in,
                              bf16* __restrict__ outHi, bf16* __restrict__ outLo,
                              int colbase, float s) {
    __shared__ float t[32][33];
    int d0 = blockIdx.x * 32, r0 = blockIdx.y * 32;
    int tx = threadIdx.x, ty = threadIdx.y;     // 32 x 8
#pragma unroll
    for (int i = 0; i < 4; i++) {
        int r = r0 + ty + i * 8;
        t[ty + i * 8][tx] = in[(long)r * DD + d0 + tx];
    }
    __syncthreads();
#pragma unroll
    for (int i = 0; i < 4; i++) {
        int d = d0 + ty + i * 8;
        float v = s * t[tx][ty + i * 8];
        bf16 h, l; hsplit(v, h, l);
        long o = (long)d * KCAT + colbase + r0 + tx;
        outHi[o] = h; outLo[o] = l;
    }
}

// ---------------- LayerNorm forward -> bf16 hi(/lo) ----------------
__global__ void ln_fwd_kernel(const float* __restrict__ x,
                              const float* __restrict__ grad,
                              bf16* __restrict__ ghi, bf16* __restrict__ glo,
                              const float* __restrict__ gamma,
                              const float* __restrict__ delta,
                              float* meanOut, float* rstdOut, int useLr) {
    int t = blockIdx.x, z = blockIdx.z, tid = threadIdx.x;
    const float lr = useLr ? c_lrs[z] : 0.f;
    const float* xr = x + (long)t * DD;
    float v[3]; float s = 0.f;
#pragma unroll
    for (int i = 0; i < 3; i++) {
        int c = tid + i * 256;
        float xv = xr[c];
        if (useLr) xv -= lr * grad[(long)t * DD + c];
        v[i] = xv; s += xv;
    }
    __shared__ float red[256];
    red[tid] = s; __syncthreads();
    for (int o = 128; o; o >>= 1) { if (tid < o) red[tid] += red[tid + o]; __syncthreads(); }
    float mu = red[0] * (1.f / DD);
    __syncthreads();
    float s2 = 0.f;
#pragma unroll
    for (int i = 0; i < 3; i++) { float dv = v[i] - mu; s2 += dv * dv; }
    red[tid] = s2; __syncthreads();
    for (int o = 128; o; o >>= 1) { if (tid < o) red[tid] += red[tid + o]; __syncthreads(); }
    float rs = rsqrtf(red[0] * (1.f / DD) + 1e-5f);
    long base = (long)z * NELEM + (long)t * DD;
#pragma unroll
    for (int i = 0; i < 3; i++) {
        int c = tid + i * 256;
        float gv = gamma[c] * (v[i] - mu) * rs + delta[c];
        bf16 h, l; hsplit(gv, h, l);
        ghi[base + c] = h;
        if (glo != nullptr) glo[(long)t * DD + c] = l;
    }
    if (!useLr && tid == 0) { meanOut[t] = mu; rstdOut[t] = rs; }
}

// ---------------- LayerNorm backward ----------------
__global__ void ln_bwd_kernel(const float* __restrict__ x,
                              const float* __restrict__ mean,
                              const float* __restrict__ rstd,
                              const float* __restrict__ gamma,
                              const float* __restrict__ dgv,
                              float* __restrict__ dx) {
    int t = blockIdx.x, tid = threadIdx.x;
    float mu = mean[t], rs = rstd[t];
    const float* xr = x + (long)t * DD;
    const float* dr = dgv + (long)t * DD;
    float xh[3], dxh[3]; float s1 = 0.f, s2 = 0.f;
#pragma unroll
    for (int i = 0; i < 3; i++) {
        int c = tid + i * 256;
        xh[i]  = (xr[c] - mu) * rs;
        dxh[i] = dr[c] * gamma[c];
        s1 += dxh[i]; s2 += dxh[i] * xh[i];
    }
    __shared__ float r1[256], r2[256];
    r1[tid] = s1; r2[tid] = s2; __syncthreads();
    for (int o = 128; o; o >>= 1) {
        if (tid < o) { r1[tid] += r1[tid + o]; r2[tid] += r2[tid + o]; }
        __syncthreads();
    }
    float m1 = r1[0] * (1.f / DD), m2 = r2[0] * (1.f / DD);
#pragma unroll
    for (int i = 0; i < 3; i++) {
        int c = tid + i * 256;
        dx[(long)t * DD + c] = rs * (dxh[i] - m1 - xh[i] * m2);
    }
}

// ---------------- bf16 GEMM, 64x64 tile, 128 thr, ldmatrix + precomputed hi/lo ----------------
// NTERM=3: acc += Ah*Bh + Ah*Bl + Al*Bh.  NTERM=1: single term.
// FUSED=1: B = whi (+wlo) concat rows [4608][K]; region n0<768 -> CK float,
//          n0<1536 -> CQ float, else epiH (1: relu -> Ahi/Alo + energy; 2: energy only).
// FUSED=0: plain; C = CK float, ld = DD, epi = 0 (dgrad).
__device__ __forceinline__ void mma16(float* c, const unsigned* a, const unsigned* b) {
    asm volatile("mma.sync.aligned.m16n8k16.row.col.f32.bf16.bf16.f32 "
                 "{%0,%1,%2,%3}, {%4,%5,%6,%7}, {%8,%9}, {%0,%1,%2,%3};"
                 : "+f"(c[0]), "+f"(c[1]), "+f"(c[2]), "+f"(c[3])
                 : "r"(a[0]), "r"(a[1]), "r"(a[2]), "r"(a[3]),
                   "r"(b[0]), "r"(b[1]));
}

__device__ __forceinline__ void ldsm4(unsigned& r0, unsigned& r1, unsigned& r2, unsigned& r3,
                                      unsigned addr) {
    asm volatile("ldmatrix.sync.aligned.m8n8.x4.shared.b16 {%0,%1,%2,%3}, [%4];"
                 : "=r"(r0), "=r"(r1), "=r"(r2), "=r"(r3) : "r"(addr));
}

template <int NTERM, int FUSED>
__global__ void __launch_bounds__(128, 4)
gemm_k(const bf16* __restrict__ Ahi, const bf16* __restrict__ Alo,
       const bf16* __restrict__ Bhi, const bf16* __restrict__ Blo,
       float* __restrict__ CK, float* __restrict__ CQ,
       bf16* __restrict__ CHhi, bf16* __restrict__ CHlo,
       int Mrows, int Kdim, int epiH,
       double* e_base, int e_per_z, long strideAz, long strideCz) {
    constexpr int NS = (NTERM == 3) ? 2 : 1;
    __shared__ unsigned sA[2][NS][512];   // 64 rows x 8 u32, 16B-chunk swizzled
    __shared__ unsigned sB[2][NS][512];

    const int tid = threadIdx.x;
    const int m0 = blockIdx.y * 64;
    const int n0 = blockIdx.x * 64;

    const bf16* Bh = Bhi + (long)n0 * Kdim;
    const bf16* Bl = (NS == 2) ? (Blo + (long)n0 * Kdim) : nullptr;

    float* Cf; int ncol, epi;
    if (FUSED) {
        if (n0 < DD)          { Cf = CK; ncol = n0;      epi = 0; }
        else if (n0 < 2 * DD) { Cf = CQ; ncol = n0 - DD; epi = 0; }
        else                  { Cf = nullptr; ncol = n0; epi = epiH; }
    } else {
        Cf = CK; ncol = n0; epi = 0;
    }
    Ahi += (long)blockIdx.z * strideAz;
    if (NS == 2) Alo += (long)blockIdx.z * strideAz;
    if (Cf != nullptr) Cf += (long)blockIdx.z * strideCz;

    const int wid = tid >> 5, lane = tid & 31;
    const int wm = (wid >> 1) * 32, wn = (wid & 1) * 32;
    const int gr = lane >> 2, tg = lane & 3;

    // ldmatrix lane addresses (bytes into one 2048B tile)
    unsigned sAb = (unsigned)__cvta_generic_to_shared(&sA[0][0][0]);
    unsigned sBb = (unsigned)__cvta_generic_to_shared(&sB[0][0][0]);
    const int t8 = lane & 7;
    unsigned aAddr[2], bAddr[2];
    {
        int q = lane >> 3;
#pragma unroll
        for (int mi = 0; mi < 2; mi++) {
            int row = wm + mi * 16 + (q & 1) * 8 + t8;
            int ch = q >> 1;
            int line = row >> 2;
            int pos = (row & 3) * 2 + (ch ^ (line & 1));
            aAddr[mi] = sAb + line * 128 + pos * 16;
        }
        int halfB = (lane >> 4) & 1, chB = (lane >> 3) & 1;
#pragma unroll
        for (int jp = 0; jp < 2; jp++) {
            int row = wn + jp * 16 + halfB * 8 + t8;
            int line = row >> 2;
            int pos = (row & 3) * 2 + (chB ^ (line & 1));
            bAddr[jp] = sBb + line * 128 + pos * 16;
        }
    }

    float acc[2][4][4];
#pragma unroll
    for (int i = 0; i < 2; i++)
#pragma unroll
        for (int j = 0; j < 4; j++)
#pragma unroll
            for (int t = 0; t < 4; t++) acc[i][j][t] = 0.f;

    // per-thread load slot: row r = tid>>1 (0..63), chunk h = tid&1 (k half)
    const int lr_ = tid >> 1, lh = tid & 1;
    const int sline = lr_ >> 2;
    const int spos  = (lr_ & 3) * 2 + (lh ^ (sline & 1));
    const int sidx  = sline * 32 + spos * 4;           // u32 index
    uint4 va[NS], vb[NS];

    auto loadG = [&](int k0) {
        bool okA = (m0 + lr_) < Mrows;
        long aoff = (long)(m0 + lr_) * Kdim + k0 + lh * 8;
        va[0] = okA ? *(const uint4*)(Ahi + aoff) : make_uint4(0u, 0u, 0u, 0u);
        long boff = (long)lr_ * Kdim + k0 + lh * 8;
        vb[0] = *(const uint4*)(Bh + boff);
        if (NS == 2) {
            va[NS - 1] = okA ? *(const uint4*)(Alo + aoff) : make_uint4(0u, 0u, 0u, 0u);
            vb[NS - 1] = *(const uint4*)(Bl + boff);
        }
    };

    auto storeS = [&](int buf) {
        *(uint4*)&sA[buf][0][sidx] = va[0];
        *(uint4*)&sB[buf][0][sidx] = vb[0];
        if (NS == 2) {
            *(uint4*)&sA[buf][NS - 1][sidx] = va[NS - 1];
            *(uint4*)&sB[buf][NS - 1][sidx] = vb[NS - 1];
        }
    };

    auto compute = [&](int buf) {
        unsigned a[NS][2][4], b[NS][4][2];
#pragma unroll
        for (int s = 0; s < NS; s++) {
            unsigned off = (unsigned)((buf * NS + s) * 2048);
#pragma unroll
            for (int mi = 0; mi < 2; mi++)
                ldsm4(a[s][mi][0], a[s][mi][1], a[s][mi][2], a[s][mi][3], aAddr[mi] + off);
#pragma unroll
            for (int jp = 0; jp < 2; jp++) {
                unsigned r0, r1, r2, r3;
                ldsm4(r0, r1, r2, r3, bAddr[jp] + off);
                b[s][jp * 2][0] = r0; b[s][jp * 2][1] = r1;
                b[s][jp * 2 + 1][0] = r2; b[s][jp * 2 + 1][1] = r3;
            }
        }
#pragma unroll
        for (int mi = 0; mi < 2; mi++)
#pragma unroll
            for (int j = 0; j < 4; j++) {
                mma16(acc[mi][j], a[0][mi], b[0][j]);          // Ah*Bh
                if (NS == 2) {
                    mma16(acc[mi][j], a[0][mi], b[NS - 1][j]); // Ah*Bl
                    mma16(acc[mi][j], a[NS - 1][mi], b[0][j]); // Al*Bh
                }
            }
    };

    const int nK = Kdim / 16;
    loadG(0);
    storeS(0);
    __syncthreads();
    for (int kt = 0; kt < nK; kt++) {
        int buf = kt & 1;
        bool hasNext = (kt + 1 < nK);
        if (hasNext) loadG((kt + 1) * 16);
        compute(buf);
        if (hasNext) storeS(buf ^ 1);
        __syncthreads();
    }

    if (epi == 0) {
#pragma unroll
        for (int mi = 0; mi < 2; mi++)
#pragma unroll
            for (int half = 0; half < 2; half++) {
                int row = m0 + wm + mi * 16 + half * 8 + gr;
                if (row >= Mrows) continue;
                float* Cr = Cf + (long)row * DD + ncol + wn;
#pragma unroll
                for (int j = 0; j < 4; j++) {
                    int col = j * 8 + tg * 2;
                    Cr[col]     = acc[mi][j][half * 2 + 0];
                    Cr[col + 1] = acc[mi][j][half * 2 + 1];
                }
            }
    } else {
        double le = 0.0;
#pragma unroll
        for (int mi = 0; mi < 2; mi++)
#pragma unroll
            for (int half = 0; half < 2; half++) {
                int row = m0 + wm + mi * 16 + half * 8 + gr;
                if (row >= Mrows) continue;
                long ob = (long)row * KCAT + ncol + wn;
#pragma unroll
                for (int j = 0; j < 4; j++) {
                    int col = j * 8 + tg * 2;
                    float c0 = acc[mi][j][half * 2 + 0];
                    float c1 = acc[mi][j][half * 2 + 1];
                    float r0 = c0 > 0.f ? c0 : 0.f;
                    float r1 = c1 > 0.f ? c1 : 0.f;
                    le += (double)r0 * (double)r0 + (double)r1 * (double)r1;
                    if (epi == 1) {
                        bf16 h, l;
                        hsplit(r0, h, l); CHhi[ob + col] = h;     CHlo[ob + col] = l;
                        hsplit(r1, h, l); CHhi[ob + col + 1] = h; CHlo[ob + col + 1] = l;
                    }
                }
            }
        __shared__ double ered[128];
        ered[tid] = le; __syncthreads();
        for (int o = 64; o; o >>= 1) {
            if (tid < o) ered[tid] += ered[tid + o];
            __syncthreads();
        }
        if (tid == 0)
            atomicAdd(e_base + (e_per_z ? blockIdx.z : 0), -0.5 * ered[0]);
    }
}

// ---------------- attention ----------------
#define ATT_LD 68
#define ATT_SMEM ((196*ATT_LD*2 + 196 + 8*200) * 4)

template <bool GRAD>
__global__ void __launch_bounds__(256)
att_kernel(const float* __restrict__ Kall, const float* __restrict__ Qall,
           bf16* __restrict__ dHi, bf16* __restrict__ dLo,
           double* e_base, int e_per_z) {
    extern __shared__ float sm[];
    const int LD = ATT_LD;
    float* Ksh = sm;
    float* Qsh = Ksh + 196 * LD;
    float* lse = Qsh + 196 * LD;
    float* rowbuf = lse + 196;
    __shared__ double wsum[8];

    int bh = blockIdx.x; int b = bh / NH; int h = bh % NH;
    long base = (long)blockIdx.z * NELEM + (long)b * NTOK * DD + h * HD;
    const float* Kg = Kall + base;
    const float* Qg = Qall + base;
    int tid = threadIdx.x, w = tid >> 5, lane = tid & 31;

    for (int i = tid; i < 196 * 16; i += 256) {
        int r = i >> 4, c4 = (i & 15) << 2;
        *(float4*)(Ksh + r * LD + c4) = *(const float4*)(Kg + (long)r * DD + c4);
        *(float4*)(Qsh + r * LD + c4) = *(const float4*)(Qg + (long)r * DD + c4);
    }
    __syncthreads();

    double lsesum = 0.0;
    float* rb = rowbuf + w * 200;

    for (int q = w; q < 196; q += 8) {
        const float4* Qr4 = (const float4*)(Qsh + q * LD);
        float mx = -1e30f;
        for (int k = lane; k < 196; k += 32) {
            const float4* Kr4 = (const float4*)(Ksh + k * LD);
            float s = 0.f;
#pragma unroll
            for (int y = 0; y < 16; y++) {
                float4 a = Kr4[y], b4 = Qr4[y];
                s = fmaf(a.x, b4.x, s); s = fmaf(a.y, b4.y, s);
                s = fmaf(a.z, b4.z, s); s = fmaf(a.w, b4.w, s);
            }
            s *= BETA;
            rb[k] = s;
            mx = fmaxf(mx, s);
        }
#pragma unroll
        for (int o = 16; o; o >>= 1) mx = fmaxf(mx, __shfl_xor_sync(0xffffffffu, mx, o));
        float se = 0.f;
        for (int k = lane; k < 196; k += 32) {
            float e = expf(rb[k] - mx);
            se += e;
            if (GRAD) rb[k] = e;
        }
#pragma unroll
        for (int o = 16; o; o >>= 1) se += __shfl_xor_sync(0xffffffffu, se, o);
        float l = mx + logf(se);
        if (lane == 0) lsesum += (double)l;
        if (GRAD) {
            if (lane == 0) lse[q] = l;
            float inv = 1.f / se;
            for (int k = lane; k < 196; k += 32) rb[k] *= inv;
            __syncwarp();
            int y0 = lane, y1 = lane + 32;
            float a0 = 0.f, a1 = 0.f;
            for (int k = 0; k < 196; k++) {
                float p = rb[k];
                a0 = fmaf(p, Ksh[k * LD + y0], a0);
                a1 = fmaf(p, Ksh[k * LD + y1], a1);
            }
            // dQ -> Acat col block [768, 1536)
            long o = (long)(b * NTOK + q) * KCAT + DD + h * HD;
            bf16 hh, ll;
            hsplit(-a0, hh, ll); dHi[o + y0] = hh; dLo[o + y0] = ll;
            hsplit(-a1, hh, ll); dHi[o + y1] = hh; dLo[o + y1] = ll;
            __syncwarp();
        }
    }

    if (lane == 0) wsum[w] = lsesum;
    __syncthreads();
    if (tid == 0) {
        double t = 0.0;
        for (int i = 0; i < 8; i++) t += wsum[i];
        atomicAdd(e_base + (e_per_z ? blockIdx.z : 0), -(double)INVB * t);
    }

    if (GRAD) {
        __syncthreads();   // lse[] complete
        for (int k = w; k < 196; k += 8) {
            const float4* Kr4 = (const float4*)(Ksh + k * LD);
            for (int q = lane; q < 196; q += 32) {
                const float4* Qr4 = (const float4*)(Qsh + q * LD);
                float s = 0.f;
#pragma unroll
                for (int y = 0; y < 16; y++) {
                    float4 a = Kr4[y], b4 = Qr4[y];
                    s = fmaf(a.x, b4.x, s); s = fmaf(a.y, b4.y, s);
                    s = fmaf(a.z, b4.z, s); s = fmaf(a.w, b4.w, s);
                }
                rb[q] = expf(BETA * s - lse[q]);
            }
            __syncwarp();
            int y0 = lane, y1 = lane + 32;
            float a0 = 0.f, a1 = 0.f;
            for (int q = 0; q < 196; q++) {
                float p = rb[q];
                a0 = fmaf(p, Qsh[q * LD + y0], a0);
                a1 = fmaf(p, Qsh[q * LD + y1], a1);
            }
            // dK -> Acat col block [0, 768)
            long o = (long)(b * NTOK + k) * KCAT + h * HD;
            bf16 hh, ll;
            hsplit(-a0, hh, ll); dHi[o + y0] = hh; dLo[o + y0] = ll;
            hsplit(-a1, hh, ll); dHi[o + y1] = hh; dLo[o + y1] = ll;
            __syncwarp();
        }
    }
}

// ---------------- host driver ----------------
extern "C" void kernel_launch(void* const* d_in, const int* in_sizes, int n_in,
                              void* d_out, int out_size) {
    const float* x     = (const float*)d_in[0];
    const float* gamma = (const float*)d_in[1];
    const float* delta = (const float*)d_in[2];
    const float* wk    = (const float*)d_in[3];
    const float* wq    = (const float*)d_in[4];
    const float* xi    = (const float*)d_in[5];
    float* out = (float*)d_out;

    bf16 *ghi, *glo, *Ahi, *Alo, *whi, *wlo, *BThi, *BTlo;
    float *K, *Q, *dg, *gr, *mean, *rstd;
    double *eref, *ecand;
    cudaGetSymbolAddress((void**)&ghi,  d_ghi);
    cudaGetSymbolAddress((void**)&glo,  d_glo);
    cudaGetSymbolAddress((void**)&K,    d_K);
    cudaGetSymbolAddress((void**)&Q,    d_Q);
    cudaGetSymbolAddress((void**)&Ahi,  d_Ahi);
    cudaGetSymbolAddress((void**)&Alo,  d_Alo);
    cudaGetSymbolAddress((void**)&whi,  d_whi);
    cudaGetSymbolAddress((void**)&wlo,  d_wlo);
    cudaGetSymbolAddress((void**)&BThi, d_BThi);
    cudaGetSymbolAddress((void**)&BTlo, d_BTlo);
    cudaGetSymbolAddress((void**)&dg,   d_dg);
    cudaGetSymbolAddress((void**)&gr,   d_gr);
    cudaGetSymbolAddress((void**)&mean, d_mean);
    cudaGetSymbolAddress((void**)&rstd, d_rstd);
    cudaGetSymbolAddress((void**)&eref,  d_eref);
    cudaGetSymbolAddress((void**)&ecand, d_ecand);

    cudaFuncSetAttribute(att_kernel<true>,  cudaFuncAttributeMaxDynamicSharedMemorySize, ATT_SMEM);
    cudaFuncSetAttribute(att_kernel<false>, cudaFuncAttributeMaxDynamicSharedMemorySize, ATT_SMEM);

    const long sZ = (long)NELEM;
    const int MB = (BN + 63) / 64;     // 25

    zero_kernel<<<1, 32>>>();

    // operand prep (bf16 hi/lo, once)
    w2bf_kernel<<<(int)(((long)KCAT * DD + 255) / 256), 256>>>(wk, wq, xi, whi, wlo);
    btprep_kernel<<<dim3(DD / 32, DD / 32), dim3(32, 8)>>>(wk, BThi, BTlo, 0, 1.f);
    btprep_kernel<<<dim3(DD / 32, DD / 32), dim3(32, 8)>>>(wq, BThi, BTlo, DD, 1.f);
    btprep_kernel<<<dim3(DD / 32, MHOP / 32), dim3(32, 8)>>>(xi, BThi, BTlo, 2 * DD, -1.f);

    // ---- main pass (split-3 bf16, near-fp32) ----
    ln_fwd_kernel<<<dim3(BN, 1, 1), 256>>>(x, nullptr, ghi, glo, gamma, delta, mean, rstd, 0);

    // fused K/Q/h: one N=4608 launch; h -> relu (bf16 hi/lo into Acat) + eref
    gemm_k<3, 1><<<dim3(KCAT / 64, MB), 128>>>(
        ghi, glo, whi, wlo, K, Q, Ahi, Alo,
        BN, DD, /*epiH=*/1, eref, 0, 0, 0);

    att_kernel<true><<<dim3(BB_ * NH, 1, 1), 256, ATT_SMEM>>>(K, Q, Ahi, Alo, eref, 0);

    // fused dgrad: dg = Acat @ BT^T   (K = 4608)
    gemm_k<3, 0><<<dim3(DD / 64, MB), 128>>>(
        Ahi, Alo, BThi, BTlo, dg, nullptr, nullptr, nullptr,
        BN, KCAT, /*epiH=*/0, nullptr, 0, 0, 0);

    ln_bwd_kernel<<<BN, 256>>>(x, mean, rstd, gamma, dg, gr);

    // ---- Armijo candidates (z = 4): single-term bf16, energies only ----
    ln_fwd_kernel<<<dim3(BN, 1, 4), 256>>>(x, gr, ghi, nullptr, gamma, delta, nullptr, nullptr, 1);

    gemm_k<1, 1><<<dim3(KCAT / 64, MB, 4), 128>>>(
        ghi, nullptr, whi, nullptr, K, Q, nullptr, nullptr,
        BN, DD, /*epiH=*/2, ecand, 1, sZ, sZ);

    att_kernel<false><<<dim3(BB_ * NH, 1, 4), 256, ATT_SMEM>>>(K, Q, nullptr, nullptr, ecand, 1);

    select_kernel<<<1, 1>>>();
    update_kernel<<<(NELEM + 255) / 256, 256>>>(x, gr, out);
}

// round 13
// speedup vs baseline: 2.6340x; 1.2312x over previous
#include <cuda_runtime.h>
#include <cuda_bf16.h>
#include <math.h>

// ---------------- problem constants ----------------
#define BB_   8
#define NTOK  196
#define DD    768
#define NH    12
#define HD    64
#define MHOP  3072
#define BN    (BB_*NTOK)          // 1568
#define NELEM (BN*DD)             // 1204224
#define KCAT  4608                // 768 + 768 + 3072
#define BETA  0.125f
#define INVB  8.0f

typedef __nv_bfloat16 bf16;

// ---------------- scratch ----------------
__device__ __align__(256) bf16  d_ghi[4L*BN*DD];
__device__ __align__(256) bf16  d_glo[(long)BN*DD];
__device__ __align__(256) float d_K  [4L*BN*DD];
__device__ __align__(256) float d_Q  [4L*BN*DD];
__device__ __align__(256) bf16  d_Ahi[(long)BN*KCAT];    // [dK | dQ | h] hi
__device__ __align__(256) bf16  d_Alo[(long)BN*KCAT];    // lo
__device__ __align__(256) bf16  d_whi[(long)KCAT*DD];    // [wk|wq|xi] hi
__device__ __align__(256) bf16  d_wlo[(long)KCAT*DD];
__device__ __align__(256) bf16  d_BThi[(long)DD*KCAT];   // [WkT|WqT|-XiT] hi
__device__ __align__(256) bf16  d_BTlo[(long)DD*KCAT];
__device__ __align__(256) float d_dg [BN*DD];
__device__ __align__(256) float d_gr [BN*DD];
__device__ float  d_mean[BN];
__device__ float  d_rstd[BN];
__device__ double d_eref;
__device__ double d_ecand[4];
__device__ float  d_chosen;
__constant__ float c_lrs[4] = {1.0f, 0.5f, 0.25f, 0.125f};

// ---------------- helpers ----------------
__device__ __forceinline__ void hsplit(float v, bf16& h, bf16& l) {
    h = __float2bfloat16_rn(v);
    l = __float2bfloat16_rn(v - __bfloat162float(h));
}

// ---------------- tiny kernels ----------------
__global__ void zero_kernel() {
    if (threadIdx.x == 0) d_eref = 0.0;
    if (threadIdx.x < 4)  d_ecand[threadIdx.x] = 0.0;
}

__global__ void select_kernel() {
    if (threadIdx.x == 0) {
        double eref = d_eref;
        float chosen = 0.0625f;
        if (d_ecand[3] < eref) chosen = 0.125f;
        if (d_ecand[2] < eref) chosen = 0.25f;
        if (d_ecand[1] < eref) chosen = 0.5f;
        if (d_ecand[0] < eref) chosen = 1.0f;
        d_chosen = chosen;
    }
}

__global__ void update_kernel(const float* __restrict__ x,
                              const float* __restrict__ grad,
                              float* __restrict__ out) {
    int i = blockIdx.x * 256 + threadIdx.x;
    if (i < NELEM) out[i] = x[i] - d_chosen * grad[i];
}

// weights -> concat bf16 hi/lo  [4608][768]
__global__ void w2bf_kernel(const float* __restrict__ wk,
                            const float* __restrict__ wq,
                            const float* __restrict__ xi,
                            bf16* __restrict__ whi, bf16* __restrict__ wlo) {
    long i = (long)blockIdx.x * 256 + threadIdx.x;
    if (i >= (long)KCAT * DD) return;
    long n = i / DD;
    float v;
    if (n < DD)           v = wk[i];
    else if (n < 2 * DD)  v = wq[i - (long)DD * DD];
    else                  v = xi[i - 2L * DD * DD];
    bf16 h, l; hsplit(v, h, l);
    whi[i] = h; wlo[i] = l;
}

// outHi/Lo[d][colbase + r] = hi/lo(s * in[r][d]);   out row stride KCAT
__global__ void btprep_kernel(const float* __restrict__ in,
                              bf16* __restrict__ outHi, bf16* __restrict__ outLo,
                              int colbase, float s) {
    __shared__ float t[32][33];
    int d0 = blockIdx.x * 32, r0 = blockIdx.y * 32;
    int tx = threadIdx.x, ty = threadIdx.y;     // 32 x 8
#pragma unroll
    for (int i = 0; i < 4; i++) {
        int r = r0 + ty + i * 8;
        t[ty + i * 8][tx] = in[(long)r * DD + d0 + tx];
    }
    __syncthreads();
#pragma unroll
    for (int i = 0; i < 4; i++) {
        int d = d0 + ty + i * 8;
        float v = s * t[tx][ty + i * 8];
        bf16 h, l; hsplit(v, h, l);
        long o = (long)d * KCAT + colbase + r0 + tx;
        outHi[o] = h; outLo[o] = l;
    }
}

// ---------------- LayerNorm forward -> bf16 hi(/lo) ----------------
__global__ void ln_fwd_kernel(const float* __restrict__ x,
                              const float* __restrict__ grad,
                              bf16* __restrict__ ghi, bf16* __restrict__ glo,
                              const float* __restrict__ gamma,
                              const float* __restrict__ delta,
                              float* meanOut, float* rstdOut, int useLr) {
    int t = blockIdx.x, z = blockIdx.z, tid = threadIdx.x;
    const float lr = useLr ? c_lrs[z] : 0.f;
    const float* xr = x + (long)t * DD;
    float v[3]; float s = 0.f;
#pragma unroll
    for (int i = 0; i < 3; i++) {
        int c = tid + i * 256;
        float xv = xr[c];
        if (useLr) xv -= lr * grad[(long)t * DD + c];
        v[i] = xv; s += xv;
    }
    __shared__ float red[256];
    red[tid] = s; __syncthreads();
    for (int o = 128; o; o >>= 1) { if (tid < o) red[tid] += red[tid + o]; __syncthreads(); }
    float mu = red[0] * (1.f / DD);
    __syncthreads();
    float s2 = 0.f;
#pragma unroll
    for (int i = 0; i < 3; i++) { float dv = v[i] - mu; s2 += dv * dv; }
    red[tid] = s2; __syncthreads();
    for (int o = 128; o; o >>= 1) { if (tid < o) red[tid] += red[tid + o]; __syncthreads(); }
    float rs = rsqrtf(red[0] * (1.f / DD) + 1e-5f);
    long base = (long)z * NELEM + (long)t * DD;
#pragma unroll
    for (int i = 0; i < 3; i++) {
        int c = tid + i * 256;
        float gv = gamma[c] * (v[i] - mu) * rs + delta[c];
        bf16 h, l; hsplit(gv, h, l);
        ghi[base + c] = h;
        if (glo != nullptr) glo[(long)t * DD + c] = l;
    }
    if (!useLr && tid == 0) { meanOut[t] = mu; rstdOut[t] = rs; }
}

// ---------------- LayerNorm backward ----------------
__global__ void ln_bwd_kernel(const float* __restrict__ x,
                              const float* __restrict__ mean,
                              const float* __restrict__ rstd,
                              const float* __restrict__ gamma,
                              const float* __restrict__ dgv,
                              float* __restrict__ dx) {
    int t = blockIdx.x, tid = threadIdx.x;
    float mu = mean[t], rs = rstd[t];
    const float* xr = x + (long)t * DD;
    const float* dr = dgv + (long)t * DD;
    float xh[3], dxh[3]; float s1 = 0.f, s2 = 0.f;
#pragma unroll
    for (int i = 0; i < 3; i++) {
        int c = tid + i * 256;
        xh[i]  = (xr[c] - mu) * rs;
        dxh[i] = dr[c] * gamma[c];
        s1 += dxh[i]; s2 += dxh[i] * xh[i];
    }
    __shared__ float r1[256], r2[256];
    r1[tid] = s1; r2[tid] = s2; __syncthreads();
    for (int o = 128; o; o >>= 1) {
        if (tid < o) { r1[tid] += r1[tid + o]; r2[tid] += r2[tid + o]; }
        __syncthreads();
    }
    float m1 = r1[0] * (1.f / DD), m2 = r2[0] * (1.f / DD);
#pragma unroll
    for (int i = 0; i < 3; i++) {
        int c = tid + i * 256;
        dx[(long)t * DD + c] = rs * (dxh[i] - m1 - xh[i] * m2);
    }
}

// ---------------- bf16 GEMM: 128x64x32 tile, 128 thr, cp.async + ldmatrix ----------------
// Warp tile 64x32 (2 m-warps x 2 n-warps). Rows are 32 bf16 = 64B = 4 x 16B chunks;
// swizzle: line = row>>1 (128B), slot = (row&1)*4 + (ch ^ (line&3)).
// NTERM=3: acc += Ah*Bh + Ah*Bl + Al*Bh.  NTERM=1: single term.
// FUSED=1: concat-B [4608][K]: n0<768 -> CK float, n0<1536 -> CQ float, else epiH.
// FUSED=0: plain C=CK float ld DD (dgrad).
__device__ __forceinline__ void mma16(float* c, const unsigned* a, const unsigned* b) {
    asm volatile("mma.sync.aligned.m16n8k16.row.col.f32.bf16.bf16.f32 "
                 "{%0,%1,%2,%3}, {%4,%5,%6,%7}, {%8,%9}, {%0,%1,%2,%3};"
                 : "+f"(c[0]), "+f"(c[1]), "+f"(c[2]), "+f"(c[3])
                 : "r"(a[0]), "r"(a[1]), "r"(a[2]), "r"(a[3]),
                   "r"(b[0]), "r"(b[1]));
}

__device__ __forceinline__ void ldsm4(unsigned& r0, unsigned& r1, unsigned& r2, unsigned& r3,
                                      unsigned addr) {
    asm volatile("ldmatrix.sync.aligned.m8n8.x4.shared.b16 {%0,%1,%2,%3}, [%4];"
                 : "=r"(r0), "=r"(r1), "=r"(r2), "=r"(r3) : "r"(addr));
}

__device__ __forceinline__ void cpa16(unsigned sa, const void* ga, int sz) {
    asm volatile("cp.async.cg.shared.global [%0], [%1], 16, %2;"
                 :: "r"(sa), "l"(ga), "r"(sz));
}

template <int NTERM, int FUSED>
__global__ void __launch_bounds__(128, 3)
gemm_k(const bf16* __restrict__ Ahi, const bf16* __restrict__ Alo,
       const bf16* __restrict__ Bhi, const bf16* __restrict__ Blo,
       float* __restrict__ CK, float* __restrict__ CQ,
       bf16* __restrict__ CHhi, bf16* __restrict__ CHlo,
       int Mrows, int Kdim, int epiH,
       double* e_base, int e_per_z, long strideAz, long strideCz) {
    constexpr int NS = (NTERM == 3) ? 2 : 1;
    // A: 128 rows x 32 bf16 = 8KB per split per buf; B: 64 rows = 4KB
    __shared__ unsigned sA[2 * NS * 2048];
    __shared__ unsigned sB[2 * NS * 1024];

    const int tid = threadIdx.x;
    const int m0 = blockIdx.y * 128;
    const int n0 = blockIdx.x * 64;

    const bf16* Bh = Bhi + (long)n0 * Kdim;
    const bf16* Bl = (NS == 2) ? (Blo + (long)n0 * Kdim) : nullptr;

    float* Cf; int ncol, epi;
    if (FUSED) {
        if (n0 < DD)          { Cf = CK; ncol = n0;      epi = 0; }
        else if (n0 < 2 * DD) { Cf = CQ; ncol = n0 - DD; epi = 0; }
        else                  { Cf = nullptr; ncol = n0; epi = epiH; }
    } else {
        Cf = CK; ncol = n0; epi = 0;
    }
    Ahi += (long)blockIdx.z * strideAz;
    if (NS == 2) Alo += (long)blockIdx.z * strideAz;
    if (Cf != nullptr) Cf += (long)blockIdx.z * strideCz;

    const int wid = tid >> 5, lane = tid & 31;
    const int wm = (wid >> 1) * 64, wn = (wid & 1) * 32;
    const int gr = lane >> 2, tg = lane & 3;

    unsigned sAb = (unsigned)__cvta_generic_to_shared(sA);
    unsigned sBb = (unsigned)__cvta_generic_to_shared(sB);

    // ldmatrix lane addresses: A frags (4 m16 per warp) x 2 k-halves, B (2 n16) x 2
    unsigned aAddr[2][4], bAddr[2][2];
    {
        const int t8 = lane & 7;
        const int q = lane >> 3;
#pragma unroll
        for (int h = 0; h < 2; h++) {
#pragma unroll
            for (int mi = 0; mi < 4; mi++) {
                int row = wm + mi * 16 + (q & 1) * 8 + t8;
                int ch = h * 2 + (q >> 1);
                int line = row >> 1;
                int slot = (row & 1) * 4 + (ch ^ (line & 3));
                aAddr[h][mi] = sAb + line * 128 + slot * 16;
            }
            int halfB = (lane >> 4) & 1, chB = (lane >> 3) & 1;
#pragma unroll
            for (int jp = 0; jp < 2; jp++) {
                int row = wn + jp * 16 + halfB * 8 + t8;
                int ch = h * 2 + chB;
                int line = row >> 1;
                int slot = (row & 1) * 4 + (ch ^ (line & 3));
                bAddr[h][jp] = sBb + line * 128 + slot * 16;
            }
        }
    }

    float acc[4][4][4];
#pragma unroll
    for (int i = 0; i < 4; i++)
#pragma unroll
        for (int j = 0; j < 4; j++)
#pragma unroll
            for (int t = 0; t < 4; t++) acc[i][j][t] = 0.f;

    auto loadG = [&](int k0, int buf) {
#pragma unroll
        for (int s = 0; s < NS; s++) {
            const bf16* src = (s == 0) ? Ahi : Alo;
#pragma unroll
            for (int i = 0; i < 4; i++) {       // A: 512 chunks / 128 thr
                int id = tid + i * 128;
                int row = id >> 2, ch = id & 3;
                int line = row >> 1;
                int slot = (row & 1) * 4 + (ch ^ (line & 3));
                unsigned sa = sAb + (buf * NS + s) * 8192 + line * 128 + slot * 16;
                int grow = m0 + row;
                bool ok = grow < Mrows;
                const bf16* gp = src + (long)(ok ? grow : 0) * Kdim + k0 + ch * 8;
                cpa16(sa, gp, ok ? 16 : 0);
            }
        }
#pragma unroll
        for (int s = 0; s < NS; s++) {
            const bf16* src = (s == 0) ? Bh : Bl;
#pragma unroll
            for (int i = 0; i < 2; i++) {       // B: 256 chunks / 128 thr
                int id = tid + i * 128;
                int row = id >> 2, ch = id & 3;
                int line = row >> 1;
                int slot = (row & 1) * 4 + (ch ^ (line & 3));
                unsigned sa = sBb + (buf * NS + s) * 4096 + line * 128 + slot * 16;
                cpa16(sa, src + (long)row * Kdim + k0 + ch * 8, 16);
            }
        }
        asm volatile("cp.async.commit_group;");
    };

    auto compute = [&](int buf) {
#pragma unroll
        for (int h = 0; h < 2; h++) {
            unsigned a[NS][4][4], b[NS][4][2];
#pragma unroll
            for (int s = 0; s < NS; s++) {
                unsigned aOff = (unsigned)((buf * NS + s) * 8192);
                unsigned bOff = (unsigned)((buf * NS + s) * 4096);
#pragma unroll
                for (int mi = 0; mi < 4; mi++)
                    ldsm4(a[s][mi][0], a[s][mi][1], a[s][mi][2], a[s][mi][3],
                          aAddr[h][mi] + aOff);
#pragma unroll
                for (int jp = 0; jp < 2; jp++) {
                    unsigned r0, r1, r2, r3;
                    ldsm4(r0, r1, r2, r3, bAddr[h][jp] + bOff);
                    b[s][jp * 2][0] = r0; b[s][jp * 2][1] = r1;
                    b[s][jp * 2 + 1][0] = r2; b[s][jp * 2 + 1][1] = r3;
                }
            }
#pragma unroll
            for (int mi = 0; mi < 4; mi++)
#pragma unroll
                for (int j = 0; j < 4; j++) {
                    mma16(acc[mi][j], a[0][mi], b[0][j]);          // Ah*Bh
                    if (NS == 2) {
                        mma16(acc[mi][j], a[0][mi], b[NS - 1][j]); // Ah*Bl
                        mma16(acc[mi][j], a[NS - 1][mi], b[0][j]); // Al*Bh
                    }
                }
        }
    };

    const int nK = Kdim / 32;
    loadG(0, 0);
    for (int kt = 0; kt < nK; kt++) {
        int buf = kt & 1;
        asm volatile("cp.async.wait_group 0;");
        __syncthreads();
        if (kt + 1 < nK) loadG((kt + 1) * 32, buf ^ 1);
        compute(buf);
    }

    if (epi == 0) {
#pragma unroll
        for (int mi = 0; mi < 4; mi++)
#pragma unroll
            for (int half = 0; half < 2; half++) {
                int row = m0 + wm + mi * 16 + half * 8 + gr;
                if (row >= Mrows) continue;
                float* Cr = Cf + (long)row * DD + ncol + wn;
#pragma unroll
                for (int j = 0; j < 4; j++) {
                    int col = j * 8 + tg * 2;
                    Cr[col]     = acc[mi][j][half * 2 + 0];
                    Cr[col + 1] = acc[mi][j][half * 2 + 1];
                }
            }
    } else {
        double le = 0.0;
#pragma unroll
        for (int mi = 0; mi < 4; mi++)
#pragma unroll
            for (int half = 0; half < 2; half++) {
                int row = m0 + wm + mi * 16 + half * 8 + gr;
                if (row >= Mrows) continue;
                long ob = (long)row * KCAT + ncol + wn;
#pragma unroll
                for (int j = 0; j < 4; j++) {
                    int col = j * 8 + tg * 2;
                    float c0 = acc[mi][j][half * 2 + 0];
                    float c1 = acc[mi][j][half * 2 + 1];
                    float r0 = c0 > 0.f ? c0 : 0.f;
                    float r1 = c1 > 0.f ? c1 : 0.f;
                    le += (double)r0 * (double)r0 + (double)r1 * (double)r1;
                    if (epi == 1) {
                        bf16 h, l;
                        hsplit(r0, h, l); CHhi[ob + col] = h;     CHlo[ob + col] = l;
                        hsplit(r1, h, l); CHhi[ob + col + 1] = h; CHlo[ob + col + 1] = l;
                    }
                }
            }
        __shared__ double ered[128];
        ered[tid] = le; __syncthreads();
        for (int o = 64; o; o >>= 1) {
            if (tid < o) ered[tid] += ered[tid + o];
            __syncthreads();
        }
        if (tid == 0)
            atomicAdd(e_base + (e_per_z ? blockIdx.z : 0), -0.5 * ered[0]);
    }
}

// ---------------- attention ----------------
#define ATT_LD 68
#define ATT_SMEM ((196*ATT_LD*2 + 196 + 8*200) * 4)

template <bool GRAD>
__global__ void __launch_bounds__(256)
att_kernel(const float* __restrict__ Kall, const float* __restrict__ Qall,
           bf16* __restrict__ dHi, bf16* __restrict__ dLo,
           double* e_base, int e_per_z) {
    extern __shared__ float sm[];
    const int LD = ATT_LD;
    float* Ksh = sm;
    float* Qsh = Ksh + 196 * LD;
    float* lse = Qsh + 196 * LD;
    float* rowbuf = lse + 196;
    __shared__ double wsum[8];

    int bh = blockIdx.x; int b = bh / NH; int h = bh % NH;
    long base = (long)blockIdx.z * NELEM + (long)b * NTOK * DD + h * HD;
    const float* Kg = Kall + base;
    const float* Qg = Qall + base;
    int tid = threadIdx.x, w = tid >> 5, lane = tid & 31;

    for (int i = tid; i < 196 * 16; i += 256) {
        int r = i >> 4, c4 = (i & 15) << 2;
        *(float4*)(Ksh + r * LD + c4) = *(const float4*)(Kg + (long)r * DD + c4);
        *(float4*)(Qsh + r * LD + c4) = *(const float4*)(Qg + (long)r * DD + c4);
    }
    __syncthreads();

    double lsesum = 0.0;
    float* rb = rowbuf + w * 200;

    for (int q = w; q < 196; q += 8) {
        const float4* Qr4 = (const float4*)(Qsh + q * LD);
        float mx = -1e30f;
        for (int k = lane; k < 196; k += 32) {
            const float4* Kr4 = (const float4*)(Ksh + k * LD);
            float s = 0.f;
#pragma unroll
            for (int y = 0; y < 16; y++) {
                float4 a = Kr4[y], b4 = Qr4[y];
                s = fmaf(a.x, b4.x, s); s = fmaf(a.y, b4.y, s);
                s = fmaf(a.z, b4.z, s); s = fmaf(a.w, b4.w, s);
            }
            s *= BETA;
            rb[k] = s;
            mx = fmaxf(mx, s);
        }
#pragma unroll
        for (int o = 16; o; o >>= 1) mx = fmaxf(mx, __shfl_xor_sync(0xffffffffu, mx, o));
        float se = 0.f;
        for (int k = lane; k < 196; k += 32) {
            float e = expf(rb[k] - mx);
            se += e;
            if (GRAD) rb[k] = e;
        }
#pragma unroll
        for (int o = 16; o; o >>= 1) se += __shfl_xor_sync(0xffffffffu, se, o);
        float l = mx + logf(se);
        if (lane == 0) lsesum += (double)l;
        if (GRAD) {
            if (lane == 0) lse[q] = l;
            float inv = 1.f / se;
            for (int k = lane; k < 196; k += 32) rb[k] *= inv;
            __syncwarp();
            int y0 = lane, y1 = lane + 32;
            float a0 = 0.f, a1 = 0.f;
            for (int k = 0; k < 196; k++) {
                float p = rb[k];
                a0 = fmaf(p, Ksh[k * LD + y0], a0);
                a1 = fmaf(p, Ksh[k * LD + y1], a1);
            }
            long o = (long)(b * NTOK + q) * KCAT + DD + h * HD;
            bf16 hh, ll;
            hsplit(-a0, hh, ll); dHi[o + y0] = hh; dLo[o + y0] = ll;
            hsplit(-a1, hh, ll); dHi[o + y1] = hh; dLo[o + y1] = ll;
            __syncwarp();
        }
    }

    if (lane == 0) wsum[w] = lsesum;
    __syncthreads();
    if (tid == 0) {
        double t = 0.0;
        for (int i = 0; i < 8; i++) t += wsum[i];
        atomicAdd(e_base + (e_per_z ? blockIdx.z : 0), -(double)INVB * t);
    }

    if (GRAD) {
        __syncthreads();   // lse[] complete
        for (int k = w; k < 196; k += 8) {
            const float4* Kr4 = (const float4*)(Ksh + k * LD);
            for (int q = lane; q < 196; q += 32) {
                const float4* Qr4 = (const float4*)(Qsh + q * LD);
                float s = 0.f;
#pragma unroll
                for (int y = 0; y < 16; y++) {
                    float4 a = Kr4[y], b4 = Qr4[y];
                    s = fmaf(a.x, b4.x, s); s = fmaf(a.y, b4.y, s);
                    s = fmaf(a.z, b4.z, s); s = fmaf(a.w, b4.w, s);
                }
                rb[q] = expf(BETA * s - lse[q]);
            }
            __syncwarp();
            int y0 = lane, y1 = lane + 32;
            float a0 = 0.f, a1 = 0.f;
            for (int q = 0; q < 196; q++) {
                float p = rb[q];
                a0 = fmaf(p, Qsh[q * LD + y0], a0);
                a1 = fmaf(p, Qsh[q * LD + y1], a1);
            }
            long o = (long)(b * NTOK + k) * KCAT + h * HD;
            bf16 hh, ll;
            hsplit(-a0, hh, ll); dHi[o + y0] = hh; dLo[o + y0] = ll;
            hsplit(-a1, hh, ll); dHi[o + y1] = hh; dLo[o + y1] = ll;
            __syncwarp();
        }
    }
}

// ---------------- host driver ----------------
extern "C" void kernel_launch(void* const* d_in, const int* in_sizes, int n_in,
                              void* d_out, int out_size) {
    const float* x     = (const float*)d_in[0];
    const float* gamma = (const float*)d_in[1];
    const float* delta = (const float*)d_in[2];
    const float* wk    = (const float*)d_in[3];
    const float* wq    = (const float*)d_in[4];
    const float* xi    = (const float*)d_in[5];
    float* out = (float*)d_out;

    bf16 *ghi, *glo, *Ahi, *Alo, *whi, *wlo, *BThi, *BTlo;
    float *K, *Q, *dg, *gr, *mean, *rstd;
    double *eref, *ecand;
    cudaGetSymbolAddress((void**)&ghi,  d_ghi);
    cudaGetSymbolAddress((void**)&glo,  d_glo);
    cudaGetSymbolAddress((void**)&K,    d_K);
    cudaGetSymbolAddress((void**)&Q,    d_Q);
    cudaGetSymbolAddress((void**)&Ahi,  d_Ahi);
    cudaGetSymbolAddress((void**)&Alo,  d_Alo);
    cudaGetSymbolAddress((void**)&whi,  d_whi);
    cudaGetSymbolAddress((void**)&wlo,  d_wlo);
    cudaGetSymbolAddress((void**)&BThi, d_BThi);
    cudaGetSymbolAddress((void**)&BTlo, d_BTlo);
    cudaGetSymbolAddress((void**)&dg,   d_dg);
    cudaGetSymbolAddress((void**)&gr,   d_gr);
    cudaGetSymbolAddress((void**)&mean, d_mean);
    cudaGetSymbolAddress((void**)&rstd, d_rstd);
    cudaGetSymbolAddress((void**)&eref,  d_eref);
    cudaGetSymbolAddress((void**)&ecand, d_ecand);

    cudaFuncSetAttribute(att_kernel<true>,  cudaFuncAttributeMaxDynamicSharedMemorySize, ATT_SMEM);
    cudaFuncSetAttribute(att_kernel<false>, cudaFuncAttributeMaxDynamicSharedMemorySize, ATT_SMEM);

    const long sZ = (long)NELEM;
    const int MB = (BN + 127) / 128;     // 13

    zero_kernel<<<1, 32>>>();

    // operand prep (bf16 hi/lo, once)
    w2bf_kernel<<<(int)(((long)KCAT * DD + 255) / 256), 256>>>(wk, wq, xi, whi, wlo);
    btprep_kernel<<<dim3(DD / 32, DD / 32), dim3(32, 8)>>>(wk, BThi, BTlo, 0, 1.f);
    btprep_kernel<<<dim3(DD / 32, DD / 32), dim3(32, 8)>>>(wq, BThi, BTlo, DD, 1.f);
    btprep_kernel<<<dim3(DD / 32, MHOP / 32), dim3(32, 8)>>>(xi, BThi, BTlo, 2 * DD, -1.f);

    // ---- main pass (split-3 bf16, near-fp32) ----
    ln_fwd_kernel<<<dim3(BN, 1, 1), 256>>>(x, nullptr, ghi, glo, gamma, delta, mean, rstd, 0);

    // fused K/Q/h: one N=4608 launch; h -> relu (bf16 hi/lo into Acat) + eref
    gemm_k<3, 1><<<dim3(KCAT / 64, MB), 128>>>(
        ghi, glo, whi, wlo, K, Q, Ahi, Alo,
        BN, DD, /*epiH=*/1, eref, 0, 0, 0);

    att_kernel<true><<<dim3(BB_ * NH, 1, 1), 256, ATT_SMEM>>>(K, Q, Ahi, Alo, eref, 0);

    // fused dgrad: dg = Acat @ BT^T   (K = 4608)
    gemm_k<3, 0><<<dim3(DD / 64, MB), 128>>>(
        Ahi, Alo, BThi, BTlo, dg, nullptr, nullptr, nullptr,
        BN, KCAT, /*epiH=*/0, nullptr, 0, 0, 0);

    ln_bwd_kernel<<<BN, 256>>>(x, mean, rstd, gamma, dg, gr);

    // ---- Armijo candidates (z = 4): single-term bf16, energies only ----
    ln_fwd_kernel<<<dim3(BN, 1, 4), 256>>>(x, gr, ghi, nullptr, gamma, delta, nullptr, nullptr, 1);

    gemm_k<1, 1><<<dim3(KCAT / 64, MB, 4), 128>>>(
        ghi, nullptr, whi, nullptr, K, Q, nullptr, nullptr,
        BN, DD, /*epiH=*/2, ecand, 1, sZ, sZ);

    att_kernel<false><<<dim3(BB_ * NH, 1, 4), 256, ATT_SMEM>>>(K, Q, nullptr, nullptr, ecand, 1);

    select_kernel<<<1, 1>>>();
    update_kernel<<<(NELEM + 255) / 256, 256>>>(x, gr, out);
}